// round 4
// baseline (speedup 1.0000x reference)
#include <cuda_runtime.h>
#include <math.h>

#define MAXN 100000
#define MAXE 1310720
typedef unsigned long long u64;

// ---------------- scratch (device globals) ----------------------------------
__device__ int   g_is64;
__device__ int   g_deg[2][MAXN];
__device__ int   g_rs[2][MAXN + 1];
__device__ int   g_cur[2][MAXN];
__device__ int   g_src[2][MAXE];
__device__ int   g_part[2][128];
__device__ float g_yp[MAXN * 32];     // x @ W1p[0:64]
__device__ float g_yn[MAXN * 32];     // x @ W1n[0:64]
__device__ float g_sxp[MAXN * 32];    // x @ W1p[64:128] + b1p
__device__ float g_sxn[MAXN * 32];    // x @ W1n[64:128] + b1n
__device__ float g_zc[MAXN * 64];     // [zp | zn]
__device__ float g_sump[MAXN * 64];   // seg_sum(zc, pos) = [szpp | sznp]
__device__ float g_sumn[MAXN * 64];   // seg_sum(zc, neg) = [szpn | sznn]

// ---------------- helpers ---------------------------------------------------
__device__ __forceinline__ int load_idx(const void* ei, long long pos, int is64) {
    if (is64) return (int)__ldg((const long long*)ei + pos);
    return __ldg((const int*)ei + pos);
}
__device__ __forceinline__ u64 pack2(float s) {
    u64 r; asm("mov.b64 %0, {%1, %1};" : "=l"(r) : "f"(s)); return r;
}
__device__ __forceinline__ void fma2(u64& d, u64 a, u64 b) {
    asm("fma.rn.f32x2 %0, %1, %2, %0;" : "+l"(d) : "l"(a), "l"(b));
}
__device__ __forceinline__ float2 unpack2(u64 v) {
    float2 r; asm("mov.b64 {%0, %1}, %2;" : "=f"(r.x), "=f"(r.y) : "l"(v)); return r;
}
// acc[16] (32 cols as f32x2) += s * W[k][0:32]   (W in shared, uniform addr)
__device__ __forceinline__ void row_fma(u64 acc[16], const float* Ws, int k, u64 ss) {
    const u64* w = (const u64*)(Ws + k * 32);
#pragma unroll
    for (int j = 0; j < 16; j++) fma2(acc[j], ss, w[j]);
}

// ---------------- dtype detection -------------------------------------------
__global__ void detect_dtype(const unsigned int* __restrict__ p) {
    int is64 = 1;
    for (int i = 1; i < 256; i += 2)
        if (p[i] != 0u) { is64 = 0; break; }
    g_is64 = is64;
}

// ---------------- CSR build ---------------------------------------------------
__global__ void zero_deg(int n) {
    int t = blockIdx.x * blockDim.x + threadIdx.x;
    if (t < n) { g_deg[0][t] = 0; g_deg[1][t] = 0; }
}

__global__ void hist(const void* __restrict__ pe, const void* __restrict__ ne, int E) {
    int t = blockIdx.x * blockDim.x + threadIdx.x;
    if (t >= 2 * E) return;
    int list = t >= E;
    long long e = t - (list ? E : 0);
    const void* ei = list ? ne : pe;
    int d = load_idx(ei, (long long)E + e, g_is64);
    atomicAdd(&g_deg[list][d], 1);
}

__global__ void scan1(int n) {
    int a = blockIdx.y;
    int i = blockIdx.x * 1024 + threadIdx.x;
    int v = (i < n) ? g_deg[a][i] : 0;
#pragma unroll
    for (int o = 16; o; o >>= 1) v += __shfl_down_sync(~0u, v, o);
    __shared__ int sh[32];
    if ((threadIdx.x & 31) == 0) sh[threadIdx.x >> 5] = v;
    __syncthreads();
    if (threadIdx.x < 32) {
        int w = sh[threadIdx.x];
#pragma unroll
        for (int o = 16; o; o >>= 1) w += __shfl_down_sync(~0u, w, o);
        if (threadIdx.x == 0) g_part[a][blockIdx.x] = w;
    }
}

__global__ void scan2(int nb) {
    __shared__ int sh[128];
    for (int a = 0; a < 2; a++) {
        if (threadIdx.x < nb) sh[threadIdx.x] = g_part[a][threadIdx.x];
        __syncthreads();
        if (threadIdx.x == 0) {
            int run = 0;
            for (int b = 0; b < nb; b++) { int t = sh[b]; sh[b] = run; run += t; }
        }
        __syncthreads();
        if (threadIdx.x < nb) g_part[a][threadIdx.x] = sh[threadIdx.x];
        __syncthreads();
    }
}

__global__ void scan3(int n) {
    int a = blockIdx.y;
    int i = blockIdx.x * 1024 + threadIdx.x;
    __shared__ int buf[2][1024];
    int v = (i < n) ? g_deg[a][i] : 0;
    buf[0][threadIdx.x] = v;
    __syncthreads();
    int pi = 0;
#pragma unroll
    for (int off = 1; off < 1024; off <<= 1) {
        int t = buf[pi][threadIdx.x];
        if (threadIdx.x >= off) t += buf[pi][threadIdx.x - off];
        buf[pi ^ 1][threadIdx.x] = t;
        __syncthreads();
        pi ^= 1;
    }
    int incl = buf[pi][threadIdx.x];
    int excl = incl - v + g_part[a][blockIdx.x];
    if (i < n) {
        g_rs[a][i] = excl;
        g_cur[a][i] = excl;
        if (i == n - 1) g_rs[a][n] = excl + v;
    }
}

__global__ void scatter_src(const void* __restrict__ pe, const void* __restrict__ ne, int E) {
    int t = blockIdx.x * blockDim.x + threadIdx.x;
    if (t >= 2 * E) return;
    int list = t >= E;
    long long e = t - (list ? E : 0);
    const void* ei = list ? ne : pe;
    int is64 = g_is64;
    int s = load_idx(ei, e, is64);
    int d = load_idx(ei, (long long)E + e, is64);
    int p = atomicAdd(&g_cur[list][d], 1);
    g_src[list][p] = s;
}

// ---------------- projection: y = x@W[0:64], sx = x@W[64:128]+b --------------
// thread groups g in 0..3: sign = g>>1 (0=pos,1=neg), part = g&1 (0=Y,1=S)
__global__ void project1(const float* __restrict__ x,
                         const float* __restrict__ W1p, const float* __restrict__ b1p,
                         const float* __restrict__ W1n, const float* __restrict__ b1n,
                         int n) {
    __shared__ float Wp[128 * 32];
    __shared__ float Wn[128 * 32];
    for (int t = threadIdx.x; t < 128 * 32; t += blockDim.x) { Wp[t] = W1p[t]; Wn[t] = W1n[t]; }
    __syncthreads();
    int g = threadIdx.x >> 6;
    int sign = g >> 1, part = g & 1;
    int i = blockIdx.x * 64 + (threadIdx.x & 63);
    if (i >= n) return;
    const float* Ws = sign ? Wn : Wp;
    int ro = part ? 64 : 0;
    const float4* x4 = (const float4*)x + (size_t)i * 16;

    u64 acc[16];
#pragma unroll
    for (int j = 0; j < 16; j++) acc[j] = 0ULL;
#pragma unroll 4
    for (int kk = 0; kk < 16; kk++) {
        float4 v = x4[kk];
        int k = ro + kk * 4;
        row_fma(acc, Ws, k + 0, pack2(v.x));
        row_fma(acc, Ws, k + 1, pack2(v.y));
        row_fma(acc, Ws, k + 2, pack2(v.z));
        row_fma(acc, Ws, k + 3, pack2(v.w));
    }
    if (part == 0) {
        u64* yo = (u64*)((sign ? g_yn : g_yp) + (size_t)i * 32);
#pragma unroll
        for (int j = 0; j < 16; j++) yo[j] = acc[j];
    } else {
        const float2* bb = (const float2*)(sign ? b1n : b1p);
        float2* so = (float2*)((sign ? g_sxn : g_sxp) + (size_t)i * 32);
#pragma unroll
        for (int j = 0; j < 16; j++) {
            float2 f = unpack2(acc[j]);
            float2 b = __ldg(bb + j);
            so[j] = make_float2(f.x + b.x, f.y + b.y);
        }
    }
}

// ---------------- layer-1 seg-mean + activation (CSR gather, no atomics) ----
// thread = (node d, chunk c in 0..7); writes zc[d] = [tanh(...) x2 halves]
__global__ void seg1(int n) {
    int t = blockIdx.x * blockDim.x + threadIdx.x;
    int d = t >> 3, c = t & 7;
    if (d >= n) return;

    int b0 = __ldg(&g_rs[0][d]), e0 = __ldg(&g_rs[0][d + 1]);
    float4 ap = make_float4(0.f, 0.f, 0.f, 0.f);
    for (int e = b0; e < e0; e++) {
        int s = __ldg(&g_src[0][e]);
        float4 v = __ldg((const float4*)g_yp + (size_t)s * 8 + c);
        ap.x += v.x; ap.y += v.y; ap.z += v.z; ap.w += v.w;
    }
    float invp = 1.f / fmaxf((float)(e0 - b0), 1.f);

    int b1 = __ldg(&g_rs[1][d]), e1 = __ldg(&g_rs[1][d + 1]);
    float4 an = make_float4(0.f, 0.f, 0.f, 0.f);
    for (int e = b1; e < e1; e++) {
        int s = __ldg(&g_src[1][e]);
        float4 v = __ldg((const float4*)g_yn + (size_t)s * 8 + c);
        an.x += v.x; an.y += v.y; an.z += v.z; an.w += v.w;
    }
    float invn = 1.f / fmaxf((float)(e1 - b1), 1.f);

    float4 sp = __ldg((const float4*)g_sxp + (size_t)d * 8 + c);
    float4 sn = __ldg((const float4*)g_sxn + (size_t)d * 8 + c);
    float4 zp4, zn4;
    zp4.x = tanhf(fmaf(ap.x, invp, sp.x));
    zp4.y = tanhf(fmaf(ap.y, invp, sp.y));
    zp4.z = tanhf(fmaf(ap.z, invp, sp.z));
    zp4.w = tanhf(fmaf(ap.w, invp, sp.w));
    zn4.x = tanhf(fmaf(an.x, invn, sn.x));
    zn4.y = tanhf(fmaf(an.y, invn, sn.y));
    zn4.z = tanhf(fmaf(an.z, invn, sn.z));
    zn4.w = tanhf(fmaf(an.w, invn, sn.w));
    ((float4*)g_zc)[(size_t)d * 16 + c]     = zp4;
    ((float4*)g_zc)[(size_t)d * 16 + 8 + c] = zn4;
}

// ---------------- layer-2 seg-sum (CSR gather, full 64-wide zc rows) ---------
// thread = (node d, list, chunk c in 0..15); warp = one d (16 lanes/list)
__global__ void seg2(int n) {
    int t = blockIdx.x * blockDim.x + threadIdx.x;
    int d = t >> 5;
    int r = t & 31;
    int list = r >> 4, c = r & 15;
    if (d >= n) return;

    int b = __ldg(&g_rs[list][d]), e = __ldg(&g_rs[list][d + 1]);
    float4 a = make_float4(0.f, 0.f, 0.f, 0.f);
    const int* src = g_src[list];
    for (; b < e; b++) {
        int s = __ldg(&src[b]);
        float4 v = __ldg((const float4*)g_zc + (size_t)s * 16 + c);
        a.x += v.x; a.y += v.y; a.z += v.z; a.w += v.w;
    }
    float* dst = list ? g_sumn : g_sump;
    ((float4*)dst)[(size_t)d * 16 + c] = a;
}

// ---------------- layer-2 node GEMM -> output --------------------------------
// thread = (node, sign): sign from tid>>7 (warp-uniform)
__global__ void node_l2(const float* __restrict__ W2p, const float* __restrict__ b2p,
                        const float* __restrict__ W2n, const float* __restrict__ b2n,
                        float* __restrict__ out, int n) {
    __shared__ float Wp[96 * 32];
    __shared__ float Wn[96 * 32];
    for (int t = threadIdx.x; t < 96 * 32; t += blockDim.x) { Wp[t] = W2p[t]; Wn[t] = W2n[t]; }
    __syncthreads();
    int sign = threadIdx.x >> 7;
    int i = blockIdx.x * 128 + (threadIdx.x & 127);
    if (i >= n) return;

    float invp = 1.f / fmaxf((float)(__ldg(&g_rs[0][i + 1]) - __ldg(&g_rs[0][i])), 1.f);
    float invn = 1.f / fmaxf((float)(__ldg(&g_rs[1][i + 1]) - __ldg(&g_rs[1][i])), 1.f);

    // pos sign: [szpp*invp, sznn*invn, zp];  neg sign: [sznp*invp, szpn*invn, zn]
    const float4* s0 = (const float4*)(g_sump + (size_t)i * 64 + (sign ? 32 : 0));
    const float4* s1 = (const float4*)(g_sumn + (size_t)i * 64 + (sign ? 0 : 32));
    const float4* s2 = (const float4*)(g_zc   + (size_t)i * 64 + (sign ? 32 : 0));
    const float* Ws = sign ? Wn : Wp;

    u64 acc[16];
#pragma unroll
    for (int j = 0; j < 16; j++) acc[j] = 0ULL;
#pragma unroll 4
    for (int kk = 0; kk < 8; kk++) {
        float4 v = __ldg(s0 + kk); int k = kk * 4;
        row_fma(acc, Ws, k + 0, pack2(v.x * invp));
        row_fma(acc, Ws, k + 1, pack2(v.y * invp));
        row_fma(acc, Ws, k + 2, pack2(v.z * invp));
        row_fma(acc, Ws, k + 3, pack2(v.w * invp));
    }
#pragma unroll 4
    for (int kk = 0; kk < 8; kk++) {
        float4 v = __ldg(s1 + kk); int k = 32 + kk * 4;
        row_fma(acc, Ws, k + 0, pack2(v.x * invn));
        row_fma(acc, Ws, k + 1, pack2(v.y * invn));
        row_fma(acc, Ws, k + 2, pack2(v.z * invn));
        row_fma(acc, Ws, k + 3, pack2(v.w * invn));
    }
#pragma unroll 4
    for (int kk = 0; kk < 8; kk++) {
        float4 v = __ldg(s2 + kk); int k = 64 + kk * 4;
        row_fma(acc, Ws, k + 0, pack2(v.x));
        row_fma(acc, Ws, k + 1, pack2(v.y));
        row_fma(acc, Ws, k + 2, pack2(v.z));
        row_fma(acc, Ws, k + 3, pack2(v.w));
    }
    const float2* bb = (const float2*)(sign ? b2n : b2p);
    float2* o2 = (float2*)(out + (size_t)i * 64 + (sign ? 32 : 0));
#pragma unroll
    for (int j = 0; j < 16; j++) {
        float2 f = unpack2(acc[j]);
        float2 b = __ldg(bb + j);
        o2[j] = make_float2(tanhf(f.x + b.x), tanhf(f.y + b.y));
    }
}

// ---------------- launch ------------------------------------------------------
extern "C" void kernel_launch(void* const* d_in, const int* in_sizes, int n_in,
                              void* d_out, int out_size) {
    const float* x   = (const float*)d_in[0];
    const float* W1p = (const float*)d_in[1];
    const float* b1p = (const float*)d_in[2];
    const float* W1n = (const float*)d_in[3];
    const float* b1n = (const float*)d_in[4];
    const float* W2p = (const float*)d_in[5];
    const float* b2p = (const float*)d_in[6];
    const float* W2n = (const float*)d_in[7];
    const float* b2n = (const float*)d_in[8];
    const void* pe = d_in[9];
    const void* ne = d_in[10];

    int n = in_sizes[0] / 64;
    int E = in_sizes[9] / 2;
    int nb = (n + 1023) / 1024;
    float* out = (float*)d_out;

    detect_dtype<<<1, 1>>>((const unsigned int*)pe);
    zero_deg<<<(n + 255) / 256, 256>>>(n);
    hist<<<(2 * E + 255) / 256, 256>>>(pe, ne, E);
    scan1<<<dim3(nb, 2), 1024>>>(n);
    scan2<<<1, 128>>>(nb);
    scan3<<<dim3(nb, 2), 1024>>>(n);
    scatter_src<<<(2 * E + 255) / 256, 256>>>(pe, ne, E);

    project1<<<(n + 63) / 64, 256>>>(x, W1p, b1p, W1n, b1n, n);
    seg1<<<(n * 8 + 255) / 256, 256>>>(n);
    seg2<<<(n * 32 + 255) / 256, 256>>>(n);
    node_l2<<<(n + 127) / 128, 256>>>(W2p, b2p, W2n, b2n, out, n);
}

// round 5
// speedup vs baseline: 1.2739x; 1.2739x over previous
#include <cuda_runtime.h>
#include <math.h>

#define MAXN 100000
typedef unsigned long long u64;

// ---------------- scratch (device globals) ----------------------------------
__device__ int   g_is64;
__device__ float g_yp[MAXN * 32];     // x @ W1p[0:64]
__device__ float g_yn[MAXN * 32];     // x @ W1n[0:64]
__device__ float g_sxp[MAXN * 32];    // x @ W1p[64:128] + b1p
__device__ float g_sxn[MAXN * 32];    // x @ W1n[64:128] + b1n
__device__ float g_apsum[MAXN * 32];  // seg_sum(yp, pos)
__device__ float g_ansum[MAXN * 32];  // seg_sum(yn, neg)
__device__ float g_cntp[MAXN];
__device__ float g_cntn[MAXN];
__device__ float g_zc[MAXN * 64];     // [zp | zn] per node, 256B rows
__device__ float g_sump[MAXN * 64];   // seg_sum(zc, pos) = [szpp | sznp]
__device__ float g_sumn[MAXN * 64];   // seg_sum(zc, neg) = [szpn | sznn]

// ---------------- helpers ---------------------------------------------------
__device__ __forceinline__ void red_add_v4(float* addr, float4 v) {
    asm volatile("red.global.add.v4.f32 [%0], {%1, %2, %3, %4};"
                 :: "l"(addr), "f"(v.x), "f"(v.y), "f"(v.z), "f"(v.w)
                 : "memory");
}
__device__ __forceinline__ int load_idx(const void* ei, long long pos, int is64) {
    if (is64) return (int)__ldg((const long long*)ei + pos);
    return __ldg((const int*)ei + pos);
}
__device__ __forceinline__ u64 pack2(float s) {
    u64 r; asm("mov.b64 %0, {%1, %1};" : "=l"(r) : "f"(s)); return r;
}
__device__ __forceinline__ void fma2(u64& d, u64 a, u64 b) {
    asm("fma.rn.f32x2 %0, %1, %2, %0;" : "+l"(d) : "l"(a), "l"(b));
}
__device__ __forceinline__ float2 unpack2(u64 v) {
    float2 r; asm("mov.b64 {%0, %1}, %2;" : "=f"(r.x), "=f"(r.y) : "l"(v)); return r;
}
__device__ __forceinline__ void row_fma(u64 acc[16], const float* Ws, int k, u64 ss) {
    const u64* w = (const u64*)(Ws + k * 32);
#pragma unroll
    for (int j = 0; j < 16; j++) fma2(acc[j], ss, w[j]);
}

// ---------------- dtype detection -------------------------------------------
__global__ void detect_dtype(const unsigned int* __restrict__ p) {
    int is64 = 1;
    for (int i = 1; i < 256; i += 2)
        if (p[i] != 0u) { is64 = 0; break; }
    g_is64 = is64;
}

// ---------------- zero scatter targets ---------------------------------------
__global__ void zero_all(int n) {
    const float4 z = make_float4(0.f, 0.f, 0.f, 0.f);
    int tid = blockIdx.x * blockDim.x + threadIdx.x;
    int stride = gridDim.x * blockDim.x;
    int n8 = n * 8, n16 = n * 16;
    for (int i = tid; i < n8; i += stride) {
        ((float4*)g_apsum)[i] = z; ((float4*)g_ansum)[i] = z;
    }
    for (int i = tid; i < n16; i += stride) {
        ((float4*)g_sump)[i] = z; ((float4*)g_sumn)[i] = z;
    }
    for (int i = tid; i < n; i += stride) { g_cntp[i] = 0.f; g_cntn[i] = 0.f; }
}

// ---------------- projection: y = x@W[0:64], sx = x@W[64:128]+b --------------
// 4 groups of 64 threads: sign = g>>1, part = g&1 (0 = Y, 1 = S)
__global__ void project1(const float* __restrict__ x,
                         const float* __restrict__ W1p, const float* __restrict__ b1p,
                         const float* __restrict__ W1n, const float* __restrict__ b1n,
                         int n) {
    __shared__ float Wp[128 * 32];
    __shared__ float Wn[128 * 32];
    for (int t = threadIdx.x; t < 128 * 32; t += blockDim.x) { Wp[t] = W1p[t]; Wn[t] = W1n[t]; }
    __syncthreads();
    int g = threadIdx.x >> 6;
    int sign = g >> 1, part = g & 1;
    int i = blockIdx.x * 64 + (threadIdx.x & 63);
    if (i >= n) return;
    const float* Ws = sign ? Wn : Wp;
    int ro = part ? 64 : 0;
    const float4* x4 = (const float4*)x + (size_t)i * 16;

    u64 acc[16];
#pragma unroll
    for (int j = 0; j < 16; j++) acc[j] = 0ULL;
#pragma unroll 4
    for (int kk = 0; kk < 16; kk++) {
        float4 v = x4[kk];
        int k = ro + kk * 4;
        row_fma(acc, Ws, k + 0, pack2(v.x));
        row_fma(acc, Ws, k + 1, pack2(v.y));
        row_fma(acc, Ws, k + 2, pack2(v.z));
        row_fma(acc, Ws, k + 3, pack2(v.w));
    }
    if (part == 0) {
        u64* yo = (u64*)((sign ? g_yn : g_yp) + (size_t)i * 32);
#pragma unroll
        for (int j = 0; j < 16; j++) yo[j] = acc[j];
    } else {
        const float2* bb = (const float2*)(sign ? b1n : b1p);
        float2* so = (float2*)((sign ? g_sxn : g_sxp) + (size_t)i * 32);
#pragma unroll
        for (int j = 0; j < 16; j++) {
            float2 f = unpack2(acc[j]);
            float2 b = __ldg(bb + j);
            so[j] = make_float2(f.x + b.x, f.y + b.y);
        }
    }
}

// ---------------- layer-1 edge scatter (projected, 32-wide) + counts ---------
__global__ void edge1(const void* __restrict__ pe, const void* __restrict__ ne, int E) {
    const int is64 = g_is64;
    long long total = (long long)E * 16;  // 2E edges * 8 items
    long long stride = (long long)gridDim.x * blockDim.x;
    for (long long item = (long long)blockIdx.x * blockDim.x + threadIdx.x;
         item < total; item += stride) {
        long long e2 = item >> 3;
        int c = (int)(item & 7);
        bool pos = e2 < E;
        const void* ei = pos ? pe : ne;
        long long e = pos ? e2 : e2 - E;
        const float* y = pos ? g_yp : g_yn;
        float* sum = pos ? g_apsum : g_ansum;
        float* cnt = pos ? g_cntp : g_cntn;
        int s = load_idx(ei, e, is64);
        int d = load_idx(ei, (long long)E + e, is64);
        float4 v = __ldg((const float4*)y + (size_t)s * 8 + c);
        red_add_v4(sum + (size_t)d * 32 + c * 4, v);
        if (c == 0) atomicAdd(cnt + d, 1.0f);
    }
}

// ---------------- layer-1 activation (node x chunk parallel) -----------------
__global__ void node1b(int n) {
    int t = blockIdx.x * blockDim.x + threadIdx.x;
    int d = t >> 3, c = t & 7;
    if (d >= n) return;
    float invp = 1.f / fmaxf(g_cntp[d], 1.f);
    float invn = 1.f / fmaxf(g_cntn[d], 1.f);
    float4 a = __ldg((const float4*)g_apsum + (size_t)d * 8 + c);
    float4 s = __ldg((const float4*)g_sxp + (size_t)d * 8 + c);
    float4 o;
    o.x = tanhf(fmaf(a.x, invp, s.x));
    o.y = tanhf(fmaf(a.y, invp, s.y));
    o.z = tanhf(fmaf(a.z, invp, s.z));
    o.w = tanhf(fmaf(a.w, invp, s.w));
    ((float4*)g_zc)[(size_t)d * 16 + c] = o;
    a = __ldg((const float4*)g_ansum + (size_t)d * 8 + c);
    s = __ldg((const float4*)g_sxn + (size_t)d * 8 + c);
    o.x = tanhf(fmaf(a.x, invn, s.x));
    o.y = tanhf(fmaf(a.y, invn, s.y));
    o.z = tanhf(fmaf(a.z, invn, s.z));
    o.w = tanhf(fmaf(a.w, invn, s.w));
    ((float4*)g_zc)[(size_t)d * 16 + 8 + c] = o;
}

// ---------------- layer-2 edge scatter (zc rows, branch-free) ----------------
__global__ void edge2(const void* __restrict__ pe, const void* __restrict__ ne, int E) {
    const int is64 = g_is64;
    long long total = (long long)E * 32;  // 2E edges * 16 items
    long long stride = (long long)gridDim.x * blockDim.x;
    for (long long item = (long long)blockIdx.x * blockDim.x + threadIdx.x;
         item < total; item += stride) {
        long long e2 = item >> 4;
        int c = (int)(item & 15);
        bool pos = e2 < E;
        const void* ei = pos ? pe : ne;
        long long e = pos ? e2 : e2 - E;
        float* sum = pos ? g_sump : g_sumn;
        int s = load_idx(ei, e, is64);
        int d = load_idx(ei, (long long)E + e, is64);
        float4 v = __ldg((const float4*)g_zc + (size_t)s * 16 + c);
        red_add_v4(sum + (size_t)d * 64 + c * 4, v);
    }
}

// ---------------- layer-2 node GEMM -> output --------------------------------
// 2 groups of 128 threads: sign = tid>>7 (warp-uniform)
__global__ void node_l2(const float* __restrict__ W2p, const float* __restrict__ b2p,
                        const float* __restrict__ W2n, const float* __restrict__ b2n,
                        float* __restrict__ out, int n) {
    __shared__ float Wp[96 * 32];
    __shared__ float Wn[96 * 32];
    for (int t = threadIdx.x; t < 96 * 32; t += blockDim.x) { Wp[t] = W2p[t]; Wn[t] = W2n[t]; }
    __syncthreads();
    int sign = threadIdx.x >> 7;
    int i = blockIdx.x * 128 + (threadIdx.x & 127);
    if (i >= n) return;

    float invp = 1.f / fmaxf(g_cntp[i], 1.f);
    float invn = 1.f / fmaxf(g_cntn[i], 1.f);

    // pos sign: [szpp*invp, sznn*invn, zp];  neg sign: [sznp*invp, szpn*invn, zn]
    const float4* s0 = (const float4*)(g_sump + (size_t)i * 64 + (sign ? 32 : 0));
    const float4* s1 = (const float4*)(g_sumn + (size_t)i * 64 + (sign ? 0 : 32));
    const float4* s2 = (const float4*)(g_zc   + (size_t)i * 64 + (sign ? 32 : 0));
    const float* Ws = sign ? Wn : Wp;

    u64 acc[16];
#pragma unroll
    for (int j = 0; j < 16; j++) acc[j] = 0ULL;
#pragma unroll 4
    for (int kk = 0; kk < 8; kk++) {
        float4 v = __ldg(s0 + kk); int k = kk * 4;
        row_fma(acc, Ws, k + 0, pack2(v.x * invp));
        row_fma(acc, Ws, k + 1, pack2(v.y * invp));
        row_fma(acc, Ws, k + 2, pack2(v.z * invp));
        row_fma(acc, Ws, k + 3, pack2(v.w * invp));
    }
#pragma unroll 4
    for (int kk = 0; kk < 8; kk++) {
        float4 v = __ldg(s1 + kk); int k = 32 + kk * 4;
        row_fma(acc, Ws, k + 0, pack2(v.x * invn));
        row_fma(acc, Ws, k + 1, pack2(v.y * invn));
        row_fma(acc, Ws, k + 2, pack2(v.z * invn));
        row_fma(acc, Ws, k + 3, pack2(v.w * invn));
    }
#pragma unroll 4
    for (int kk = 0; kk < 8; kk++) {
        float4 v = __ldg(s2 + kk); int k = 64 + kk * 4;
        row_fma(acc, Ws, k + 0, pack2(v.x));
        row_fma(acc, Ws, k + 1, pack2(v.y));
        row_fma(acc, Ws, k + 2, pack2(v.z));
        row_fma(acc, Ws, k + 3, pack2(v.w));
    }
    const float2* bb = (const float2*)(sign ? b2n : b2p);
    float2* o2 = (float2*)(out + (size_t)i * 64 + (sign ? 32 : 0));
#pragma unroll
    for (int j = 0; j < 16; j++) {
        float2 f = unpack2(acc[j]);
        float2 b = __ldg(bb + j);
        o2[j] = make_float2(tanhf(f.x + b.x), tanhf(f.y + b.y));
    }
}

// ---------------- launch ------------------------------------------------------
extern "C" void kernel_launch(void* const* d_in, const int* in_sizes, int n_in,
                              void* d_out, int out_size) {
    const float* x   = (const float*)d_in[0];
    const float* W1p = (const float*)d_in[1];
    const float* b1p = (const float*)d_in[2];
    const float* W1n = (const float*)d_in[3];
    const float* b1n = (const float*)d_in[4];
    const float* W2p = (const float*)d_in[5];
    const float* b2p = (const float*)d_in[6];
    const float* W2n = (const float*)d_in[7];
    const float* b2n = (const float*)d_in[8];
    const void* pe = d_in[9];
    const void* ne = d_in[10];

    int n = in_sizes[0] / 64;
    int E = in_sizes[9] / 2;
    float* out = (float*)d_out;

    detect_dtype<<<1, 1>>>((const unsigned int*)pe);
    zero_all<<<1184, 256>>>(n);
    project1<<<(n + 63) / 64, 256>>>(x, W1p, b1p, W1n, b1n, n);
    edge1<<<4736, 256>>>(pe, ne, E);
    node1b<<<(n * 8 + 255) / 256, 256>>>(n);
    edge2<<<4736, 256>>>(pe, ne, E);
    node_l2<<<(n + 127) / 128, 256>>>(W2p, b2p, W2n, b2n, out, n);
}

// round 8
// speedup vs baseline: 1.8011x; 1.4139x over previous
#include <cuda_runtime.h>
#include <cuda_fp16.h>
#include <cstdint>
#include <math.h>

#define MAXN 100000
typedef unsigned long long u64;
typedef unsigned int u32;

// ---------------- scratch (device globals) ----------------------------------
__device__ int   g_is64;
__device__ __align__(16) __half g_yp[MAXN * 32];    // fp16: x @ W1p[0:64]
__device__ __align__(16) __half g_yn[MAXN * 32];    // fp16: x @ W1n[0:64]
__device__ float g_sxp[MAXN * 32];                  // fp32: x @ W1p[64:128] + b1p
__device__ float g_sxn[MAXN * 32];                  // fp32: x @ W1n[64:128] + b1n
__device__ __align__(16) __half g_apsum[MAXN * 32]; // fp16 seg_sum(yp, pos)
__device__ __align__(16) __half g_ansum[MAXN * 32]; // fp16 seg_sum(yn, neg)
__device__ float g_cntp[MAXN];
__device__ float g_cntn[MAXN];
__device__ __align__(16) __half g_zc[MAXN * 64];    // fp16 [zp | zn], 128B rows
__device__ __align__(16) __half g_sump[MAXN * 64];  // fp16 seg_sum(zc, pos) = [szpp | sznp]
__device__ __align__(16) __half g_sumn[MAXN * 64];  // fp16 seg_sum(zc, neg) = [szpn | sznn]

// ---------------- helpers ---------------------------------------------------
__device__ __forceinline__ void red_add_h8(void* addr, uint4 v) {
    asm volatile("red.global.add.noftz.v4.f16x2 [%0], {%1, %2, %3, %4};"
                 :: "l"(addr), "r"(v.x), "r"(v.y), "r"(v.z), "r"(v.w)
                 : "memory");
}
__device__ __forceinline__ int load_idx(const void* ei, long long pos, int is64) {
    if (is64) return (int)__ldg((const long long*)ei + pos);
    return __ldg((const int*)ei + pos);
}
__device__ __forceinline__ u64 pack2(float s) {
    u64 r; asm("mov.b64 %0, {%1, %1};" : "=l"(r) : "f"(s)); return r;
}
__device__ __forceinline__ void fma2(u64& d, u64 a, u64 b) {
    asm("fma.rn.f32x2 %0, %1, %2, %0;" : "+l"(d) : "l"(a), "l"(b));
}
__device__ __forceinline__ float2 unpack2(u64 v) {
    float2 r; asm("mov.b64 {%0, %1}, %2;" : "=f"(r.x), "=f"(r.y) : "l"(v)); return r;
}
__device__ __forceinline__ void row_fma(u64 acc[16], const float* Ws, int k, u64 ss) {
    const u64* w = (const u64*)(Ws + k * 32);
#pragma unroll
    for (int j = 0; j < 16; j++) fma2(acc[j], ss, w[j]);
}
__device__ __forceinline__ float2 h2f(u32 w) {
    __half2 h = *reinterpret_cast<__half2*>(&w);
    return __half22float2(h);
}
__device__ __forceinline__ u32 f2h(float a, float b) {
    __half2 h = __floats2half2_rn(a, b);
    return *reinterpret_cast<u32*>(&h);
}

// ---------------- dtype detection -------------------------------------------
__global__ void detect_dtype(const unsigned int* __restrict__ p) {
    int is64 = 1;
    for (int i = 1; i < 256; i += 2)
        if (p[i] != 0u) { is64 = 0; break; }
    g_is64 = is64;
}

// ---------------- zero scatter targets ---------------------------------------
__global__ void zero_all(int n) {
    const uint4 z = make_uint4(0, 0, 0, 0);
    int tid = blockIdx.x * blockDim.x + threadIdx.x;
    int stride = gridDim.x * blockDim.x;
    int n4 = n * 4, n8 = n * 8;
    for (int i = tid; i < n4; i += stride) {
        ((uint4*)g_apsum)[i] = z; ((uint4*)g_ansum)[i] = z;
    }
    for (int i = tid; i < n8; i += stride) {
        ((uint4*)g_sump)[i] = z; ((uint4*)g_sumn)[i] = z;
    }
    for (int i = tid; i < n; i += stride) { g_cntp[i] = 0.f; g_cntn[i] = 0.f; }
}

// ---------------- projection: y(fp16) = x@W[0:64], sx(fp32) = x@W[64:128]+b --
// 4 groups of 64 threads: sign = g>>1, part = g&1 (0 = Y, 1 = S)
__global__ void project1(const float* __restrict__ x,
                         const float* __restrict__ W1p, const float* __restrict__ b1p,
                         const float* __restrict__ W1n, const float* __restrict__ b1n,
                         int n) {
    __shared__ float Wp[128 * 32];
    __shared__ float Wn[128 * 32];
    for (int t = threadIdx.x; t < 128 * 32; t += blockDim.x) { Wp[t] = W1p[t]; Wn[t] = W1n[t]; }
    __syncthreads();
    int g = threadIdx.x >> 6;
    int sign = g >> 1, part = g & 1;
    int i = blockIdx.x * 64 + (threadIdx.x & 63);
    if (i >= n) return;
    const float* Ws = sign ? Wn : Wp;
    int ro = part ? 64 : 0;
    const float4* x4 = (const float4*)x + (size_t)i * 16;

    u64 acc[16];
#pragma unroll
    for (int j = 0; j < 16; j++) acc[j] = 0ULL;
#pragma unroll 4
    for (int kk = 0; kk < 16; kk++) {
        float4 v = x4[kk];
        int k = ro + kk * 4;
        row_fma(acc, Ws, k + 0, pack2(v.x));
        row_fma(acc, Ws, k + 1, pack2(v.y));
        row_fma(acc, Ws, k + 2, pack2(v.z));
        row_fma(acc, Ws, k + 3, pack2(v.w));
    }
    if (part == 0) {
        u32 w[16];
#pragma unroll
        for (int j = 0; j < 16; j++) {
            float2 f = unpack2(acc[j]);
            w[j] = f2h(f.x, f.y);
        }
        uint4* yo = (uint4*)((sign ? g_yn : g_yp) + (size_t)i * 32);
#pragma unroll
        for (int q = 0; q < 4; q++)
            yo[q] = make_uint4(w[q * 4], w[q * 4 + 1], w[q * 4 + 2], w[q * 4 + 3]);
    } else {
        const float2* bb = (const float2*)(sign ? b1n : b1p);
        float2* so = (float2*)((sign ? g_sxn : g_sxp) + (size_t)i * 32);
#pragma unroll
        for (int j = 0; j < 16; j++) {
            float2 f = unpack2(acc[j]);
            float2 b = __ldg(bb + j);
            so[j] = make_float2(f.x + b.x, f.y + b.y);
        }
    }
}

// ---------------- layer-1 edge scatter (fp16, 64B rows) + counts -------------
__global__ void edge1(const void* __restrict__ pe, const void* __restrict__ ne, int E) {
    const int is64 = g_is64;
    long long total = (long long)E * 8;  // 2E edges * 4 items (16B each)
    long long stride = (long long)gridDim.x * blockDim.x;
    for (long long item = (long long)blockIdx.x * blockDim.x + threadIdx.x;
         item < total; item += stride) {
        long long e2 = item >> 2;
        int c = (int)(item & 3);
        bool pos = e2 < E;
        const void* ei = pos ? pe : ne;
        long long e = pos ? e2 : e2 - E;
        const __half* y = pos ? g_yp : g_yn;
        __half* sum = pos ? g_apsum : g_ansum;
        float* cnt = pos ? g_cntp : g_cntn;
        int s = load_idx(ei, e, is64);
        int d = load_idx(ei, (long long)E + e, is64);
        uint4 v = __ldg((const uint4*)y + (size_t)s * 4 + c);
        red_add_h8((uint4*)sum + (size_t)d * 4 + c, v);
        if (c == 0) atomicAdd(cnt + d, 1.0f);
    }
}

// ---------------- layer-1 activation: zc = tanh(sum*inv + sx) (fp16 out) -----
__global__ void node1b(int n) {
    int t = blockIdx.x * blockDim.x + threadIdx.x;
    int d = t >> 2, c = t & 3;
    if (d >= n) return;
    float invp = 1.f / fmaxf(g_cntp[d], 1.f);
    float invn = 1.f / fmaxf(g_cntn[d], 1.f);

    // positive half -> zc chunks [0..3]
    {
        uint4 a = __ldg((const uint4*)g_apsum + (size_t)d * 4 + c);
        float4 s0 = __ldg((const float4*)g_sxp + (size_t)d * 8 + c * 2);
        float4 s1 = __ldg((const float4*)g_sxp + (size_t)d * 8 + c * 2 + 1);
        float2 f0 = h2f(a.x), f1 = h2f(a.y), f2 = h2f(a.z), f3 = h2f(a.w);
        uint4 o;
        o.x = f2h(tanhf(fmaf(f0.x, invp, s0.x)), tanhf(fmaf(f0.y, invp, s0.y)));
        o.y = f2h(tanhf(fmaf(f1.x, invp, s0.z)), tanhf(fmaf(f1.y, invp, s0.w)));
        o.z = f2h(tanhf(fmaf(f2.x, invp, s1.x)), tanhf(fmaf(f2.y, invp, s1.y)));
        o.w = f2h(tanhf(fmaf(f3.x, invp, s1.z)), tanhf(fmaf(f3.y, invp, s1.w)));
        ((uint4*)g_zc)[(size_t)d * 8 + c] = o;
    }
    // negative half -> zc chunks [4..7]
    {
        uint4 a = __ldg((const uint4*)g_ansum + (size_t)d * 4 + c);
        float4 s0 = __ldg((const float4*)g_sxn + (size_t)d * 8 + c * 2);
        float4 s1 = __ldg((const float4*)g_sxn + (size_t)d * 8 + c * 2 + 1);
        float2 f0 = h2f(a.x), f1 = h2f(a.y), f2 = h2f(a.z), f3 = h2f(a.w);
        uint4 o;
        o.x = f2h(tanhf(fmaf(f0.x, invn, s0.x)), tanhf(fmaf(f0.y, invn, s0.y)));
        o.y = f2h(tanhf(fmaf(f1.x, invn, s0.z)), tanhf(fmaf(f1.y, invn, s0.w)));
        o.z = f2h(tanhf(fmaf(f2.x, invn, s1.x)), tanhf(fmaf(f2.y, invn, s1.y)));
        o.w = f2h(tanhf(fmaf(f3.x, invn, s1.z)), tanhf(fmaf(f3.y, invn, s1.w)));
        ((uint4*)g_zc)[(size_t)d * 8 + 4 + c] = o;
    }
}

// ---------------- layer-2 edge scatter (fp16 zc rows, 128B) ------------------
__global__ void edge2(const void* __restrict__ pe, const void* __restrict__ ne, int E) {
    const int is64 = g_is64;
    long long total = (long long)E * 16;  // 2E edges * 8 items (16B each)
    long long stride = (long long)gridDim.x * blockDim.x;
    for (long long item = (long long)blockIdx.x * blockDim.x + threadIdx.x;
         item < total; item += stride) {
        long long e2 = item >> 3;
        int c = (int)(item & 7);
        bool pos = e2 < E;
        const void* ei = pos ? pe : ne;
        long long e = pos ? e2 : e2 - E;
        __half* sum = pos ? g_sump : g_sumn;
        int s = load_idx(ei, e, is64);
        int d = load_idx(ei, (long long)E + e, is64);
        uint4 v = __ldg((const uint4*)g_zc + (size_t)s * 8 + c);
        red_add_h8((uint4*)sum + (size_t)d * 8 + c, v);
    }
}

// ---------------- layer-2 GEMM section: 32 fp16 inputs * Ws[kbase..+31] ------
__device__ __forceinline__ void gemm_sec(u64 acc[16], const float* Ws, int kbase,
                                         const uint4* sec, float scale) {
#pragma unroll
    for (int q = 0; q < 4; q++) {
        uint4 u = __ldg(sec + q);
        int k = kbase + q * 8;
        float2 f;
        f = h2f(u.x); row_fma(acc, Ws, k + 0, pack2(f.x * scale)); row_fma(acc, Ws, k + 1, pack2(f.y * scale));
        f = h2f(u.y); row_fma(acc, Ws, k + 2, pack2(f.x * scale)); row_fma(acc, Ws, k + 3, pack2(f.y * scale));
        f = h2f(u.z); row_fma(acc, Ws, k + 4, pack2(f.x * scale)); row_fma(acc, Ws, k + 5, pack2(f.y * scale));
        f = h2f(u.w); row_fma(acc, Ws, k + 6, pack2(f.x * scale)); row_fma(acc, Ws, k + 7, pack2(f.y * scale));
    }
}

// ---------------- layer-2 node GEMM -> output (fp32) --------------------------
// 2 groups of 128 threads: sign = tid>>7 (warp-uniform)
__global__ void node_l2(const float* __restrict__ W2p, const float* __restrict__ b2p,
                        const float* __restrict__ W2n, const float* __restrict__ b2n,
                        float* __restrict__ out, int n) {
    __shared__ float Wp[96 * 32];
    __shared__ float Wn[96 * 32];
    for (int t = threadIdx.x; t < 96 * 32; t += blockDim.x) { Wp[t] = W2p[t]; Wn[t] = W2n[t]; }
    __syncthreads();
    int sign = threadIdx.x >> 7;
    int i = blockIdx.x * 128 + (threadIdx.x & 127);
    if (i >= n) return;

    float invp = 1.f / fmaxf(g_cntp[i], 1.f);
    float invn = 1.f / fmaxf(g_cntn[i], 1.f);

    // pos sign: [szpp*invp, sznn*invn, zp];  neg sign: [sznp*invp, szpn*invn, zn]
    const uint4* s0 = (const uint4*)g_sump + (size_t)i * 8 + (sign ? 4 : 0);
    const uint4* s1 = (const uint4*)g_sumn + (size_t)i * 8 + (sign ? 0 : 4);
    const uint4* s2 = (const uint4*)g_zc   + (size_t)i * 8 + (sign ? 4 : 0);
    const float* Ws = sign ? Wn : Wp;

    u64 acc[16];
#pragma unroll
    for (int j = 0; j < 16; j++) acc[j] = 0ULL;
    gemm_sec(acc, Ws, 0,  s0, invp);
    gemm_sec(acc, Ws, 32, s1, invn);
    gemm_sec(acc, Ws, 64, s2, 1.0f);

    const float2* bb = (const float2*)(sign ? b2n : b2p);
    float2* o2 = (float2*)(out + (size_t)i * 64 + (sign ? 32 : 0));
#pragma unroll
    for (int j = 0; j < 16; j++) {
        float2 f = unpack2(acc[j]);
        float2 b = __ldg(bb + j);
        o2[j] = make_float2(tanhf(f.x + b.x), tanhf(f.y + b.y));
    }
}

// ---------------- launch ------------------------------------------------------
extern "C" void kernel_launch(void* const* d_in, const int* in_sizes, int n_in,
                              void* d_out, int out_size) {
    const float* x   = (const float*)d_in[0];
    const float* W1p = (const float*)d_in[1];
    const float* b1p = (const float*)d_in[2];
    const float* W1n = (const float*)d_in[3];
    const float* b1n = (const float*)d_in[4];
    const float* W2p = (const float*)d_in[5];
    const float* b2p = (const float*)d_in[6];
    const float* W2n = (const float*)d_in[7];
    const float* b2n = (const float*)d_in[8];
    const void* pe = d_in[9];
    const void* ne = d_in[10];

    int n = in_sizes[0] / 64;
    int E = in_sizes[9] / 2;
    float* out = (float*)d_out;

    detect_dtype<<<1, 1>>>((const unsigned int*)pe);
    zero_all<<<1184, 256>>>(n);
    project1<<<(n + 63) / 64, 256>>>(x, W1p, b1p, W1n, b1n, n);
    edge1<<<4736, 256>>>(pe, ne, E);
    node1b<<<(n * 4 + 255) / 256, 256>>>(n);
    edge2<<<4736, 256>>>(pe, ne, E);
    node_l2<<<(n + 127) / 128, 256>>>(W2p, b2p, W2n, b2n, out, n);
}

// round 9
// speedup vs baseline: 1.9580x; 1.0871x over previous
#include <cuda_runtime.h>
#include <cuda_fp16.h>
#include <cstdint>
#include <math.h>

#define MAXN 100000
typedef unsigned long long u64;
typedef unsigned int u32;

// ---------------- scratch (device globals) ----------------------------------
__device__ int   g_is64;
__device__ __align__(16) __half g_yp[MAXN * 32];    // fp16: x @ W1p[0:64]
__device__ __align__(16) __half g_yn[MAXN * 32];    // fp16: x @ W1n[0:64]
__device__ float g_sxp[MAXN * 32];                  // fp32: x @ W1p[64:128] + b1p
__device__ float g_sxn[MAXN * 32];                  // fp32: x @ W1n[64:128] + b1n
__device__ __align__(16) __half g_apsum[MAXN * 32]; // fp16 seg_sum(yp, pos)
__device__ __align__(16) __half g_ansum[MAXN * 32]; // fp16 seg_sum(yn, neg)
__device__ float g_cntp[MAXN];
__device__ float g_cntn[MAXN];
__device__ __align__(16) __half g_zc[MAXN * 64];    // fp16 [zp | zn], 128B rows
__device__ __align__(16) __half g_sump[MAXN * 64];  // fp16 seg_sum(zc, pos) = [szpp | sznp]
__device__ __align__(16) __half g_sumn[MAXN * 64];  // fp16 seg_sum(zc, neg) = [szpn | sznn]

// ---------------- helpers ---------------------------------------------------
__device__ __forceinline__ void red_add_h8(void* addr, uint4 v) {
    asm volatile("red.global.add.noftz.v4.f16x2 [%0], {%1, %2, %3, %4};"
                 :: "l"(addr), "r"(v.x), "r"(v.y), "r"(v.z), "r"(v.w)
                 : "memory");
}
__device__ __forceinline__ int load_idx(const void* ei, long long pos, int is64) {
    if (is64) return (int)__ldg((const long long*)ei + pos);
    return __ldg((const int*)ei + pos);
}
__device__ __forceinline__ u64 pack2(float s) {
    u64 r; asm("mov.b64 %0, {%1, %1};" : "=l"(r) : "f"(s)); return r;
}
__device__ __forceinline__ void fma2(u64& d, u64 a, u64 b) {
    asm("fma.rn.f32x2 %0, %1, %2, %0;" : "+l"(d) : "l"(a), "l"(b));
}
__device__ __forceinline__ float2 unpack2(u64 v) {
    float2 r; asm("mov.b64 {%0, %1}, %2;" : "=f"(r.x), "=f"(r.y) : "l"(v)); return r;
}
// dual-node row FMA: weight row loaded from shared ONCE, used for both nodes
__device__ __forceinline__ void row_fma2n(u64 a0[16], u64 a1[16], const float* Ws,
                                          int k, u64 s0, u64 s1) {
    const u64* w = (const u64*)(Ws + k * 32);
#pragma unroll
    for (int j = 0; j < 16; j++) {
        u64 ww = w[j];
        fma2(a0[j], s0, ww);
        fma2(a1[j], s1, ww);
    }
}
__device__ __forceinline__ float2 h2f(u32 w) {
    __half2 h = *reinterpret_cast<__half2*>(&w);
    return __half22float2(h);
}
__device__ __forceinline__ u32 f2h(float a, float b) {
    __half2 h = __floats2half2_rn(a, b);
    return *reinterpret_cast<u32*>(&h);
}

// ---------------- dtype detection -------------------------------------------
__global__ void detect_dtype(const unsigned int* __restrict__ p) {
    int is64 = 1;
    for (int i = 1; i < 256; i += 2)
        if (p[i] != 0u) { is64 = 0; break; }
    g_is64 = is64;
}

// ---------------- zero scatter targets ---------------------------------------
__global__ void zero_all(int n) {
    const uint4 z = make_uint4(0, 0, 0, 0);
    int tid = blockIdx.x * blockDim.x + threadIdx.x;
    int stride = gridDim.x * blockDim.x;
    int n4 = n * 4, n8 = n * 8;
    for (int i = tid; i < n4; i += stride) {
        ((uint4*)g_apsum)[i] = z; ((uint4*)g_ansum)[i] = z;
    }
    for (int i = tid; i < n8; i += stride) {
        ((uint4*)g_sump)[i] = z; ((uint4*)g_sumn)[i] = z;
    }
    for (int i = tid; i < n; i += stride) { g_cntp[i] = 0.f; g_cntn[i] = 0.f; }
}

// ---------------- projection (2-node blocked): y(fp16), sx(fp32) -------------
// 4 groups of 64 threads: sign = g>>1, part = g&1; each thread does 2 nodes.
__global__ void project1(const float* __restrict__ x,
                         const float* __restrict__ W1p, const float* __restrict__ b1p,
                         const float* __restrict__ W1n, const float* __restrict__ b1n,
                         int n) {
    __shared__ float Wp[128 * 32];
    __shared__ float Wn[128 * 32];
    for (int t = threadIdx.x; t < 128 * 32; t += blockDim.x) { Wp[t] = W1p[t]; Wn[t] = W1n[t]; }
    __syncthreads();
    int g = threadIdx.x >> 6;
    int sign = g >> 1, part = g & 1;
    int i0 = blockIdx.x * 128 + (threadIdx.x & 63);
    int i1 = i0 + 64;
    if (i0 >= n) return;
    bool v1 = (i1 < n);
    int i1c = v1 ? i1 : i0;  // clamp loads to a safe row

    const float* Ws = sign ? Wn : Wp;
    int ro = part ? 64 : 0;
    const float4* x0 = (const float4*)x + (size_t)i0 * 16;
    const float4* x1 = (const float4*)x + (size_t)i1c * 16;

    u64 a0[16], a1[16];
#pragma unroll
    for (int j = 0; j < 16; j++) { a0[j] = 0ULL; a1[j] = 0ULL; }
#pragma unroll 2
    for (int kk = 0; kk < 16; kk++) {
        float4 p = x0[kk];
        float4 q = x1[kk];
        int k = ro + kk * 4;
        row_fma2n(a0, a1, Ws, k + 0, pack2(p.x), pack2(q.x));
        row_fma2n(a0, a1, Ws, k + 1, pack2(p.y), pack2(q.y));
        row_fma2n(a0, a1, Ws, k + 2, pack2(p.z), pack2(q.z));
        row_fma2n(a0, a1, Ws, k + 3, pack2(p.w), pack2(q.w));
    }
    if (part == 0) {
        __half* yb = sign ? g_yn : g_yp;
        uint4* yo0 = (uint4*)(yb + (size_t)i0 * 32);
        uint4* yo1 = (uint4*)(yb + (size_t)i1 * 32);
#pragma unroll
        for (int q = 0; q < 4; q++) {
            float2 f0 = unpack2(a0[q * 4 + 0]), f1 = unpack2(a0[q * 4 + 1]);
            float2 f2 = unpack2(a0[q * 4 + 2]), f3 = unpack2(a0[q * 4 + 3]);
            yo0[q] = make_uint4(f2h(f0.x, f0.y), f2h(f1.x, f1.y), f2h(f2.x, f2.y), f2h(f3.x, f3.y));
        }
        if (v1) {
#pragma unroll
            for (int q = 0; q < 4; q++) {
                float2 f0 = unpack2(a1[q * 4 + 0]), f1 = unpack2(a1[q * 4 + 1]);
                float2 f2 = unpack2(a1[q * 4 + 2]), f3 = unpack2(a1[q * 4 + 3]);
                yo1[q] = make_uint4(f2h(f0.x, f0.y), f2h(f1.x, f1.y), f2h(f2.x, f2.y), f2h(f3.x, f3.y));
            }
        }
    } else {
        const float2* bb = (const float2*)(sign ? b1n : b1p);
        float* sb = sign ? g_sxn : g_sxp;
        float2* so0 = (float2*)(sb + (size_t)i0 * 32);
        float2* so1 = (float2*)(sb + (size_t)i1 * 32);
#pragma unroll
        for (int j = 0; j < 16; j++) {
            float2 b = __ldg(bb + j);
            float2 f = unpack2(a0[j]);
            so0[j] = make_float2(f.x + b.x, f.y + b.y);
            if (v1) {
                f = unpack2(a1[j]);
                so1[j] = make_float2(f.x + b.x, f.y + b.y);
            }
        }
    }
}

// ---------------- layer-1 edge scatter (fp16, 64B rows) + counts -------------
__global__ void edge1(const void* __restrict__ pe, const void* __restrict__ ne, int E) {
    const int is64 = g_is64;
    long long total = (long long)E * 8;  // 2E edges * 4 items (16B each)
    long long stride = (long long)gridDim.x * blockDim.x;
    for (long long item = (long long)blockIdx.x * blockDim.x + threadIdx.x;
         item < total; item += stride) {
        long long e2 = item >> 2;
        int c = (int)(item & 3);
        bool pos = e2 < E;
        const void* ei = pos ? pe : ne;
        long long e = pos ? e2 : e2 - E;
        const __half* y = pos ? g_yp : g_yn;
        __half* sum = pos ? g_apsum : g_ansum;
        float* cnt = pos ? g_cntp : g_cntn;
        int s = load_idx(ei, e, is64);
        int d = load_idx(ei, (long long)E + e, is64);
        uint4 v = __ldg((const uint4*)y + (size_t)s * 4 + c);
        red_add_h8((uint4*)sum + (size_t)d * 4 + c, v);
        if (c == 0) atomicAdd(cnt + d, 1.0f);
    }
}

// ---------------- layer-1 activation: zc = tanh(sum*inv + sx) (fp16 out) -----
__global__ void node1b(int n) {
    int t = blockIdx.x * blockDim.x + threadIdx.x;
    int d = t >> 2, c = t & 3;
    if (d >= n) return;
    float invp = 1.f / fmaxf(g_cntp[d], 1.f);
    float invn = 1.f / fmaxf(g_cntn[d], 1.f);

    // positive half -> zc chunks [0..3]
    {
        uint4 a = __ldg((const uint4*)g_apsum + (size_t)d * 4 + c);
        float4 s0 = __ldg((const float4*)g_sxp + (size_t)d * 8 + c * 2);
        float4 s1 = __ldg((const float4*)g_sxp + (size_t)d * 8 + c * 2 + 1);
        float2 f0 = h2f(a.x), f1 = h2f(a.y), f2 = h2f(a.z), f3 = h2f(a.w);
        uint4 o;
        o.x = f2h(tanhf(fmaf(f0.x, invp, s0.x)), tanhf(fmaf(f0.y, invp, s0.y)));
        o.y = f2h(tanhf(fmaf(f1.x, invp, s0.z)), tanhf(fmaf(f1.y, invp, s0.w)));
        o.z = f2h(tanhf(fmaf(f2.x, invp, s1.x)), tanhf(fmaf(f2.y, invp, s1.y)));
        o.w = f2h(tanhf(fmaf(f3.x, invp, s1.z)), tanhf(fmaf(f3.y, invp, s1.w)));
        ((uint4*)g_zc)[(size_t)d * 8 + c] = o;
    }
    // negative half -> zc chunks [4..7]
    {
        uint4 a = __ldg((const uint4*)g_ansum + (size_t)d * 4 + c);
        float4 s0 = __ldg((const float4*)g_sxn + (size_t)d * 8 + c * 2);
        float4 s1 = __ldg((const float4*)g_sxn + (size_t)d * 8 + c * 2 + 1);
        float2 f0 = h2f(a.x), f1 = h2f(a.y), f2 = h2f(a.z), f3 = h2f(a.w);
        uint4 o;
        o.x = f2h(tanhf(fmaf(f0.x, invn, s0.x)), tanhf(fmaf(f0.y, invn, s0.y)));
        o.y = f2h(tanhf(fmaf(f1.x, invn, s0.z)), tanhf(fmaf(f1.y, invn, s0.w)));
        o.z = f2h(tanhf(fmaf(f2.x, invn, s1.x)), tanhf(fmaf(f2.y, invn, s1.y)));
        o.w = f2h(tanhf(fmaf(f3.x, invn, s1.z)), tanhf(fmaf(f3.y, invn, s1.w)));
        ((uint4*)g_zc)[(size_t)d * 8 + 4 + c] = o;
    }
}

// ---------------- layer-2 edge scatter (fp16 zc rows, 128B) ------------------
__global__ void edge2(const void* __restrict__ pe, const void* __restrict__ ne, int E) {
    const int is64 = g_is64;
    long long total = (long long)E * 16;  // 2E edges * 8 items (16B each)
    long long stride = (long long)gridDim.x * blockDim.x;
    for (long long item = (long long)blockIdx.x * blockDim.x + threadIdx.x;
         item < total; item += stride) {
        long long e2 = item >> 3;
        int c = (int)(item & 7);
        bool pos = e2 < E;
        const void* ei = pos ? pe : ne;
        long long e = pos ? e2 : e2 - E;
        __half* sum = pos ? g_sump : g_sumn;
        int s = load_idx(ei, e, is64);
        int d = load_idx(ei, (long long)E + e, is64);
        uint4 v = __ldg((const uint4*)g_zc + (size_t)s * 8 + c);
        red_add_h8((uint4*)sum + (size_t)d * 8 + c, v);
    }
}

// ---------------- layer-2 dual-node GEMM section ------------------------------
__device__ __forceinline__ void gemm_sec2n(u64 a0[16], u64 a1[16], const float* Ws,
                                           int kbase, const uint4* s0p, const uint4* s1p,
                                           float sc0, float sc1) {
#pragma unroll
    for (int q = 0; q < 4; q++) {
        uint4 u0 = __ldg(s0p + q);
        uint4 u1 = __ldg(s1p + q);
        int k = kbase + q * 8;
        float2 f0, f1;
        f0 = h2f(u0.x); f1 = h2f(u1.x);
        row_fma2n(a0, a1, Ws, k + 0, pack2(f0.x * sc0), pack2(f1.x * sc1));
        row_fma2n(a0, a1, Ws, k + 1, pack2(f0.y * sc0), pack2(f1.y * sc1));
        f0 = h2f(u0.y); f1 = h2f(u1.y);
        row_fma2n(a0, a1, Ws, k + 2, pack2(f0.x * sc0), pack2(f1.x * sc1));
        row_fma2n(a0, a1, Ws, k + 3, pack2(f0.y * sc0), pack2(f1.y * sc1));
        f0 = h2f(u0.z); f1 = h2f(u1.z);
        row_fma2n(a0, a1, Ws, k + 4, pack2(f0.x * sc0), pack2(f1.x * sc1));
        row_fma2n(a0, a1, Ws, k + 5, pack2(f0.y * sc0), pack2(f1.y * sc1));
        f0 = h2f(u0.w); f1 = h2f(u1.w);
        row_fma2n(a0, a1, Ws, k + 6, pack2(f0.x * sc0), pack2(f1.x * sc1));
        row_fma2n(a0, a1, Ws, k + 7, pack2(f0.y * sc0), pack2(f1.y * sc1));
    }
}

// ---------------- layer-2 node GEMM -> output (2-node blocked) ----------------
// 2 groups of 128 threads: sign = tid>>7; each thread does nodes i and i+128.
__global__ void node_l2(const float* __restrict__ W2p, const float* __restrict__ b2p,
                        const float* __restrict__ W2n, const float* __restrict__ b2n,
                        float* __restrict__ out, int n) {
    __shared__ float Wp[96 * 32];
    __shared__ float Wn[96 * 32];
    for (int t = threadIdx.x; t < 96 * 32; t += blockDim.x) { Wp[t] = W2p[t]; Wn[t] = W2n[t]; }
    __syncthreads();
    int sign = threadIdx.x >> 7;
    int i0 = blockIdx.x * 256 + (threadIdx.x & 127);
    int i1 = i0 + 128;
    if (i0 >= n) return;
    bool v1 = (i1 < n);
    int i1c = v1 ? i1 : i0;

    float invp0 = 1.f / fmaxf(g_cntp[i0], 1.f);
    float invn0 = 1.f / fmaxf(g_cntn[i0], 1.f);
    float invp1 = 1.f / fmaxf(g_cntp[i1c], 1.f);
    float invn1 = 1.f / fmaxf(g_cntn[i1c], 1.f);

    int ho = sign ? 4 : 0;
    // pos sign: [szpp*invp, sznn*invn, zp];  neg sign: [sznp*invp, szpn*invn, zn]
    const uint4* s0a = (const uint4*)g_sump + (size_t)i0 * 8 + ho;
    const uint4* s1a = (const uint4*)g_sumn + (size_t)i0 * 8 + (4 - ho);
    const uint4* s2a = (const uint4*)g_zc   + (size_t)i0 * 8 + ho;
    const uint4* s0b = (const uint4*)g_sump + (size_t)i1c * 8 + ho;
    const uint4* s1b = (const uint4*)g_sumn + (size_t)i1c * 8 + (4 - ho);
    const uint4* s2b = (const uint4*)g_zc   + (size_t)i1c * 8 + ho;
    const float* Ws = sign ? Wn : Wp;

    u64 a0[16], a1[16];
#pragma unroll
    for (int j = 0; j < 16; j++) { a0[j] = 0ULL; a1[j] = 0ULL; }
    gemm_sec2n(a0, a1, Ws, 0,  s0a, s0b, invp0, invp1);
    gemm_sec2n(a0, a1, Ws, 32, s1a, s1b, invn0, invn1);
    gemm_sec2n(a0, a1, Ws, 64, s2a, s2b, 1.0f, 1.0f);

    const float2* bb = (const float2*)(sign ? b2n : b2p);
    float2* o0 = (float2*)(out + (size_t)i0 * 64 + (sign ? 32 : 0));
    float2* o1 = (float2*)(out + (size_t)i1 * 64 + (sign ? 32 : 0));
#pragma unroll
    for (int j = 0; j < 16; j++) {
        float2 b = __ldg(bb + j);
        float2 f = unpack2(a0[j]);
        o0[j] = make_float2(tanhf(f.x + b.x), tanhf(f.y + b.y));
        if (v1) {
            f = unpack2(a1[j]);
            o1[j] = make_float2(tanhf(f.x + b.x), tanhf(f.y + b.y));
        }
    }
}

// ---------------- launch ------------------------------------------------------
extern "C" void kernel_launch(void* const* d_in, const int* in_sizes, int n_in,
                              void* d_out, int out_size) {
    const float* x   = (const float*)d_in[0];
    const float* W1p = (const float*)d_in[1];
    const float* b1p = (const float*)d_in[2];
    const float* W1n = (const float*)d_in[3];
    const float* b1n = (const float*)d_in[4];
    const float* W2p = (const float*)d_in[5];
    const float* b2p = (const float*)d_in[6];
    const float* W2n = (const float*)d_in[7];
    const float* b2n = (const float*)d_in[8];
    const void* pe = d_in[9];
    const void* ne = d_in[10];

    int n = in_sizes[0] / 64;
    int E = in_sizes[9] / 2;
    float* out = (float*)d_out;

    detect_dtype<<<1, 1>>>((const unsigned int*)pe);
    zero_all<<<1184, 256>>>(n);
    project1<<<(n + 127) / 128, 256>>>(x, W1p, b1p, W1n, b1n, n);
    edge1<<<4736, 256>>>(pe, ne, E);
    node1b<<<(n * 4 + 255) / 256, 256>>>(n);
    edge2<<<4736, 256>>>(pe, ne, E);
    node_l2<<<(n + 255) / 256, 256>>>(W2p, b2p, W2n, b2n, out, n);
}

// round 10
// speedup vs baseline: 1.9715x; 1.0069x over previous
#include <cuda_runtime.h>
#include <cuda_fp16.h>
#include <cstdint>
#include <math.h>

#define MAXN 100000
typedef unsigned long long u64;
typedef unsigned int u32;

// ---------------- scratch (device globals) ----------------------------------
__device__ int   g_is64;
__device__ __align__(16) __half g_yp[MAXN * 32];    // fp16: x @ W1p[0:64]
__device__ __align__(16) __half g_yn[MAXN * 32];    // fp16: x @ W1n[0:64]
__device__ float g_sxp[MAXN * 32];                  // fp32: x @ W1p[64:128] + b1p
__device__ float g_sxn[MAXN * 32];                  // fp32: x @ W1n[64:128] + b1n
__device__ __align__(16) __half g_apsum[MAXN * 32]; // fp16 seg_sum(yp, pos)
__device__ __align__(16) __half g_ansum[MAXN * 32]; // fp16 seg_sum(yn, neg)
__device__ float g_cntp[MAXN];
__device__ float g_cntn[MAXN];
__device__ __align__(16) __half g_zc[MAXN * 64];    // fp16 [zp | zn], 128B rows
__device__ __align__(16) __half g_sump[MAXN * 64];  // fp16 seg_sum(zc, pos) = [szpp | sznp]
__device__ __align__(16) __half g_sumn[MAXN * 64];  // fp16 seg_sum(zc, neg) = [szpn | sznn]

// ---------------- helpers ---------------------------------------------------
__device__ __forceinline__ void red_add_h8(void* addr, uint4 v) {
    asm volatile("red.global.add.noftz.v4.f16x2 [%0], {%1, %2, %3, %4};"
                 :: "l"(addr), "r"(v.x), "r"(v.y), "r"(v.z), "r"(v.w)
                 : "memory");
}
__device__ __forceinline__ int load_idx(const void* ei, long long pos, int is64) {
    if (is64) return (int)__ldg((const long long*)ei + pos);
    return __ldg((const int*)ei + pos);
}
__device__ __forceinline__ u64 pack2(float s) {
    u64 r; asm("mov.b64 %0, {%1, %1};" : "=l"(r) : "f"(s)); return r;
}
__device__ __forceinline__ void fma2(u64& d, u64 a, u64 b) {
    asm("fma.rn.f32x2 %0, %1, %2, %0;" : "+l"(d) : "l"(a), "l"(b));
}
__device__ __forceinline__ float2 unpack2(u64 v) {
    float2 r; asm("mov.b64 {%0, %1}, %2;" : "=f"(r.x), "=f"(r.y) : "l"(v)); return r;
}
// dual-node row FMA: weight row loaded from shared ONCE, used for both nodes
__device__ __forceinline__ void row_fma2n(u64 a0[16], u64 a1[16], const float* Ws,
                                          int k, u64 s0, u64 s1) {
    const u64* w = (const u64*)(Ws + k * 32);
#pragma unroll
    for (int j = 0; j < 16; j++) {
        u64 ww = w[j];
        fma2(a0[j], s0, ww);
        fma2(a1[j], s1, ww);
    }
}
__device__ __forceinline__ float2 h2f(u32 w) {
    __half2 h = *reinterpret_cast<__half2*>(&w);
    return __half22float2(h);
}
__device__ __forceinline__ u32 f2h(float a, float b) {
    __half2 h = __floats2half2_rn(a, b);
    return *reinterpret_cast<u32*>(&h);
}

// ---------------- zero scatter targets + dtype detection ---------------------
__global__ void zero_all(const unsigned int* __restrict__ p, int n) {
    int tid = blockIdx.x * blockDim.x + threadIdx.x;
    if (tid == 0) {
        int is64 = 1;
        for (int i = 1; i < 256; i += 2)
            if (p[i] != 0u) { is64 = 0; break; }
        g_is64 = is64;
    }
    const uint4 z = make_uint4(0, 0, 0, 0);
    int stride = gridDim.x * blockDim.x;
    int n4 = n * 4, n8 = n * 8;
    for (int i = tid; i < n4; i += stride) {
        ((uint4*)g_apsum)[i] = z; ((uint4*)g_ansum)[i] = z;
    }
    for (int i = tid; i < n8; i += stride) {
        ((uint4*)g_sump)[i] = z; ((uint4*)g_sumn)[i] = z;
    }
    for (int i = tid; i < n; i += stride) { g_cntp[i] = 0.f; g_cntn[i] = 0.f; }
}

// ---------------- projection (2-node blocked): y(fp16), sx(fp32) -------------
// 4 groups of 64 threads: sign = g>>1, part = g&1; each thread does 2 nodes.
__global__ void project1(const float* __restrict__ x,
                         const float* __restrict__ W1p, const float* __restrict__ b1p,
                         const float* __restrict__ W1n, const float* __restrict__ b1n,
                         int n) {
    __shared__ float Wp[128 * 32];
    __shared__ float Wn[128 * 32];
    for (int t = threadIdx.x; t < 128 * 32; t += blockDim.x) { Wp[t] = W1p[t]; Wn[t] = W1n[t]; }
    __syncthreads();
    int g = threadIdx.x >> 6;
    int sign = g >> 1, part = g & 1;
    int i0 = blockIdx.x * 128 + (threadIdx.x & 63);
    int i1 = i0 + 64;
    if (i0 >= n) return;
    bool v1 = (i1 < n);
    int i1c = v1 ? i1 : i0;  // clamp loads to a safe row

    const float* Ws = sign ? Wn : Wp;
    int ro = part ? 64 : 0;
    const float4* x0 = (const float4*)x + (size_t)i0 * 16;
    const float4* x1 = (const float4*)x + (size_t)i1c * 16;

    u64 a0[16], a1[16];
#pragma unroll
    for (int j = 0; j < 16; j++) { a0[j] = 0ULL; a1[j] = 0ULL; }
#pragma unroll 2
    for (int kk = 0; kk < 16; kk++) {
        float4 p = x0[kk];
        float4 q = x1[kk];
        int k = ro + kk * 4;
        row_fma2n(a0, a1, Ws, k + 0, pack2(p.x), pack2(q.x));
        row_fma2n(a0, a1, Ws, k + 1, pack2(p.y), pack2(q.y));
        row_fma2n(a0, a1, Ws, k + 2, pack2(p.z), pack2(q.z));
        row_fma2n(a0, a1, Ws, k + 3, pack2(p.w), pack2(q.w));
    }
    if (part == 0) {
        __half* yb = sign ? g_yn : g_yp;
        uint4* yo0 = (uint4*)(yb + (size_t)i0 * 32);
        uint4* yo1 = (uint4*)(yb + (size_t)i1 * 32);
#pragma unroll
        for (int q = 0; q < 4; q++) {
            float2 f0 = unpack2(a0[q * 4 + 0]), f1 = unpack2(a0[q * 4 + 1]);
            float2 f2 = unpack2(a0[q * 4 + 2]), f3 = unpack2(a0[q * 4 + 3]);
            yo0[q] = make_uint4(f2h(f0.x, f0.y), f2h(f1.x, f1.y), f2h(f2.x, f2.y), f2h(f3.x, f3.y));
        }
        if (v1) {
#pragma unroll
            for (int q = 0; q < 4; q++) {
                float2 f0 = unpack2(a1[q * 4 + 0]), f1 = unpack2(a1[q * 4 + 1]);
                float2 f2 = unpack2(a1[q * 4 + 2]), f3 = unpack2(a1[q * 4 + 3]);
                yo1[q] = make_uint4(f2h(f0.x, f0.y), f2h(f1.x, f1.y), f2h(f2.x, f2.y), f2h(f3.x, f3.y));
            }
        }
    } else {
        const float2* bb = (const float2*)(sign ? b1n : b1p);
        float* sb = sign ? g_sxn : g_sxp;
        float2* so0 = (float2*)(sb + (size_t)i0 * 32);
        float2* so1 = (float2*)(sb + (size_t)i1 * 32);
#pragma unroll
        for (int j = 0; j < 16; j++) {
            float2 b = __ldg(bb + j);
            float2 f = unpack2(a0[j]);
            so0[j] = make_float2(f.x + b.x, f.y + b.y);
            if (v1) {
                f = unpack2(a1[j]);
                so1[j] = make_float2(f.x + b.x, f.y + b.y);
            }
        }
    }
}

// ---------------- layer-1 edge scatter (fp16, 64B rows) + counts -------------
__device__ __forceinline__ void edge1_body(const void* pe, const void* ne, int E,
                                           int is64, long long item) {
    long long e2 = item >> 2;
    int c = (int)(item & 3);
    bool pos = e2 < E;
    const void* ei = pos ? pe : ne;
    long long e = pos ? e2 : e2 - E;
    const __half* y = pos ? g_yp : g_yn;
    __half* sum = pos ? g_apsum : g_ansum;
    float* cnt = pos ? g_cntp : g_cntn;
    int s = load_idx(ei, e, is64);
    int d = load_idx(ei, (long long)E + e, is64);
    uint4 v = __ldg((const uint4*)y + (size_t)s * 4 + c);
    red_add_h8((uint4*)sum + (size_t)d * 4 + c, v);
    if (c == 0) atomicAdd(cnt + d, 1.0f);
}

__global__ void edge1(const void* __restrict__ pe, const void* __restrict__ ne, int E) {
    const int is64 = g_is64;
    long long total = (long long)E * 8;  // 2E edges * 4 items (16B each)
    long long stride = (long long)gridDim.x * blockDim.x;
    long long item = (long long)blockIdx.x * blockDim.x + threadIdx.x;
    for (; item + stride < total; item += 2 * stride) {
        edge1_body(pe, ne, E, is64, item);
        edge1_body(pe, ne, E, is64, item + stride);
    }
    if (item < total) edge1_body(pe, ne, E, is64, item);
}

// ---------------- layer-1 activation: zc = tanh(sum*inv + sx) (fp16 out) -----
__global__ void node1b(int n) {
    int t = blockIdx.x * blockDim.x + threadIdx.x;
    int d = t >> 2, c = t & 3;
    if (d >= n) return;
    float invp = 1.f / fmaxf(g_cntp[d], 1.f);
    float invn = 1.f / fmaxf(g_cntn[d], 1.f);

    // positive half -> zc chunks [0..3]
    {
        uint4 a = __ldg((const uint4*)g_apsum + (size_t)d * 4 + c);
        float4 s0 = __ldg((const float4*)g_sxp + (size_t)d * 8 + c * 2);
        float4 s1 = __ldg((const float4*)g_sxp + (size_t)d * 8 + c * 2 + 1);
        float2 f0 = h2f(a.x), f1 = h2f(a.y), f2 = h2f(a.z), f3 = h2f(a.w);
        uint4 o;
        o.x = f2h(tanhf(fmaf(f0.x, invp, s0.x)), tanhf(fmaf(f0.y, invp, s0.y)));
        o.y = f2h(tanhf(fmaf(f1.x, invp, s0.z)), tanhf(fmaf(f1.y, invp, s0.w)));
        o.z = f2h(tanhf(fmaf(f2.x, invp, s1.x)), tanhf(fmaf(f2.y, invp, s1.y)));
        o.w = f2h(tanhf(fmaf(f3.x, invp, s1.z)), tanhf(fmaf(f3.y, invp, s1.w)));
        ((uint4*)g_zc)[(size_t)d * 8 + c] = o;
    }
    // negative half -> zc chunks [4..7]
    {
        uint4 a = __ldg((const uint4*)g_ansum + (size_t)d * 4 + c);
        float4 s0 = __ldg((const float4*)g_sxn + (size_t)d * 8 + c * 2);
        float4 s1 = __ldg((const float4*)g_sxn + (size_t)d * 8 + c * 2 + 1);
        float2 f0 = h2f(a.x), f1 = h2f(a.y), f2 = h2f(a.z), f3 = h2f(a.w);
        uint4 o;
        o.x = f2h(tanhf(fmaf(f0.x, invn, s0.x)), tanhf(fmaf(f0.y, invn, s0.y)));
        o.y = f2h(tanhf(fmaf(f1.x, invn, s0.z)), tanhf(fmaf(f1.y, invn, s0.w)));
        o.z = f2h(tanhf(fmaf(f2.x, invn, s1.x)), tanhf(fmaf(f2.y, invn, s1.y)));
        o.w = f2h(tanhf(fmaf(f3.x, invn, s1.z)), tanhf(fmaf(f3.y, invn, s1.w)));
        ((uint4*)g_zc)[(size_t)d * 8 + 4 + c] = o;
    }
}

// ---------------- layer-2 edge scatter (fp16 zc rows, 128B) ------------------
__device__ __forceinline__ void edge2_body(const void* pe, const void* ne, int E,
                                           int is64, long long item) {
    long long e2 = item >> 3;
    int c = (int)(item & 7);
    bool pos = e2 < E;
    const void* ei = pos ? pe : ne;
    long long e = pos ? e2 : e2 - E;
    __half* sum = pos ? g_sump : g_sumn;
    int s = load_idx(ei, e, is64);
    int d = load_idx(ei, (long long)E + e, is64);
    uint4 v = __ldg((const uint4*)g_zc + (size_t)s * 8 + c);
    red_add_h8((uint4*)sum + (size_t)d * 8 + c, v);
}

__global__ void edge2(const void* __restrict__ pe, const void* __restrict__ ne, int E) {
    const int is64 = g_is64;
    long long total = (long long)E * 16;  // 2E edges * 8 items (16B each)
    long long stride = (long long)gridDim.x * blockDim.x;
    long long item = (long long)blockIdx.x * blockDim.x + threadIdx.x;
    for (; item + stride < total; item += 2 * stride) {
        edge2_body(pe, ne, E, is64, item);
        edge2_body(pe, ne, E, is64, item + stride);
    }
    if (item < total) edge2_body(pe, ne, E, is64, item);
}

// ---------------- layer-2 dual-node GEMM section ------------------------------
__device__ __forceinline__ void gemm_sec2n(u64 a0[16], u64 a1[16], const float* Ws,
                                           int kbase, const uint4* s0p, const uint4* s1p,
                                           float sc0, float sc1) {
#pragma unroll
    for (int q = 0; q < 4; q++) {
        uint4 u0 = __ldg(s0p + q);
        uint4 u1 = __ldg(s1p + q);
        int k = kbase + q * 8;
        float2 f0, f1;
        f0 = h2f(u0.x); f1 = h2f(u1.x);
        row_fma2n(a0, a1, Ws, k + 0, pack2(f0.x * sc0), pack2(f1.x * sc1));
        row_fma2n(a0, a1, Ws, k + 1, pack2(f0.y * sc0), pack2(f1.y * sc1));
        f0 = h2f(u0.y); f1 = h2f(u1.y);
        row_fma2n(a0, a1, Ws, k + 2, pack2(f0.x * sc0), pack2(f1.x * sc1));
        row_fma2n(a0, a1, Ws, k + 3, pack2(f0.y * sc0), pack2(f1.y * sc1));
        f0 = h2f(u0.z); f1 = h2f(u1.z);
        row_fma2n(a0, a1, Ws, k + 4, pack2(f0.x * sc0), pack2(f1.x * sc1));
        row_fma2n(a0, a1, Ws, k + 5, pack2(f0.y * sc0), pack2(f1.y * sc1));
        f0 = h2f(u0.w); f1 = h2f(u1.w);
        row_fma2n(a0, a1, Ws, k + 6, pack2(f0.x * sc0), pack2(f1.x * sc1));
        row_fma2n(a0, a1, Ws, k + 7, pack2(f0.y * sc0), pack2(f1.y * sc1));
    }
}

// ---------------- layer-2 node GEMM -> output (2-node blocked) ----------------
// 2 groups of 128 threads: sign = tid>>7; each thread does nodes i and i+128.
__global__ void node_l2(const float* __restrict__ W2p, const float* __restrict__ b2p,
                        const float* __restrict__ W2n, const float* __restrict__ b2n,
                        float* __restrict__ out, int n) {
    __shared__ float Wp[96 * 32];
    __shared__ float Wn[96 * 32];
    for (int t = threadIdx.x; t < 96 * 32; t += blockDim.x) { Wp[t] = W2p[t]; Wn[t] = W2n[t]; }
    __syncthreads();
    int sign = threadIdx.x >> 7;
    int i0 = blockIdx.x * 256 + (threadIdx.x & 127);
    int i1 = i0 + 128;
    if (i0 >= n) return;
    bool v1 = (i1 < n);
    int i1c = v1 ? i1 : i0;

    float invp0 = 1.f / fmaxf(g_cntp[i0], 1.f);
    float invn0 = 1.f / fmaxf(g_cntn[i0], 1.f);
    float invp1 = 1.f / fmaxf(g_cntp[i1c], 1.f);
    float invn1 = 1.f / fmaxf(g_cntn[i1c], 1.f);

    int ho = sign ? 4 : 0;
    // pos sign: [szpp*invp, sznn*invn, zp];  neg sign: [sznp*invp, szpn*invn, zn]
    const uint4* s0a = (const uint4*)g_sump + (size_t)i0 * 8 + ho;
    const uint4* s1a = (const uint4*)g_sumn + (size_t)i0 * 8 + (4 - ho);
    const uint4* s2a = (const uint4*)g_zc   + (size_t)i0 * 8 + ho;
    const uint4* s0b = (const uint4*)g_sump + (size_t)i1c * 8 + ho;
    const uint4* s1b = (const uint4*)g_sumn + (size_t)i1c * 8 + (4 - ho);
    const uint4* s2b = (const uint4*)g_zc   + (size_t)i1c * 8 + ho;
    const float* Ws = sign ? Wn : Wp;

    u64 a0[16], a1[16];
#pragma unroll
    for (int j = 0; j < 16; j++) { a0[j] = 0ULL; a1[j] = 0ULL; }
    gemm_sec2n(a0, a1, Ws, 0,  s0a, s0b, invp0, invp1);
    gemm_sec2n(a0, a1, Ws, 32, s1a, s1b, invn0, invn1);
    gemm_sec2n(a0, a1, Ws, 64, s2a, s2b, 1.0f, 1.0f);

    const float2* bb = (const float2*)(sign ? b2n : b2p);
    float2* o0 = (float2*)(out + (size_t)i0 * 64 + (sign ? 32 : 0));
    float2* o1 = (float2*)(out + (size_t)i1 * 64 + (sign ? 32 : 0));
#pragma unroll
    for (int j = 0; j < 16; j++) {
        float2 b = __ldg(bb + j);
        float2 f = unpack2(a0[j]);
        o0[j] = make_float2(tanhf(f.x + b.x), tanhf(f.y + b.y));
        if (v1) {
            f = unpack2(a1[j]);
            o1[j] = make_float2(tanhf(f.x + b.x), tanhf(f.y + b.y));
        }
    }
}

// ---------------- launch ------------------------------------------------------
extern "C" void kernel_launch(void* const* d_in, const int* in_sizes, int n_in,
                              void* d_out, int out_size) {
    const float* x   = (const float*)d_in[0];
    const float* W1p = (const float*)d_in[1];
    const float* b1p = (const float*)d_in[2];
    const float* W1n = (const float*)d_in[3];
    const float* b1n = (const float*)d_in[4];
    const float* W2p = (const float*)d_in[5];
    const float* b2p = (const float*)d_in[6];
    const float* W2n = (const float*)d_in[7];
    const float* b2n = (const float*)d_in[8];
    const void* pe = d_in[9];
    const void* ne = d_in[10];

    int n = in_sizes[0] / 64;
    int E = in_sizes[9] / 2;
    float* out = (float*)d_out;

    zero_all<<<1184, 256>>>((const unsigned int*)pe, n);
    project1<<<(n + 127) / 128, 256>>>(x, W1p, b1p, W1n, b1n, n);
    edge1<<<4736, 256>>>(pe, ne, E);
    node1b<<<(n * 4 + 255) / 256, 256>>>(n);
    edge2<<<4736, 256>>>(pe, ne, E);
    node_l2<<<(n + 255) / 256, 256>>>(W2p, b2p, W2n, b2n, out, n);
}

// round 11
// speedup vs baseline: 2.0558x; 1.0428x over previous
#include <cuda_runtime.h>
#include <cuda_fp16.h>
#include <cstdint>
#include <math.h>

#define MAXN 100000
typedef unsigned long long u64;
typedef unsigned int u32;

// ---------------- scratch (device globals) ----------------------------------
__device__ int   g_is64;
__device__ __align__(16) __half g_yp[MAXN * 32];    // fp16: x @ W1p[0:64]
__device__ __align__(16) __half g_yn[MAXN * 32];    // fp16: x @ W1n[0:64]
__device__ __align__(16) __half g_apsum[MAXN * 32]; // fp16 seg_sum(yp, pos)
__device__ __align__(16) __half g_ansum[MAXN * 32]; // fp16 seg_sum(yn, neg)
__device__ float g_cntp[MAXN];
__device__ float g_cntn[MAXN];
__device__ __align__(16) __half g_zc[MAXN * 64];    // fp16 [zp | zn], 128B rows
__device__ __align__(16) __half g_sump[MAXN * 64];  // fp16 seg_sum(zc, pos) = [szpp | sznp]
__device__ __align__(16) __half g_sumn[MAXN * 64];  // fp16 seg_sum(zc, neg) = [szpn | sznn]

// ---------------- helpers ---------------------------------------------------
__device__ __forceinline__ void red_add_h8(void* addr, uint4 v) {
    asm volatile("red.global.add.noftz.v4.f16x2 [%0], {%1, %2, %3, %4};"
                 :: "l"(addr), "r"(v.x), "r"(v.y), "r"(v.z), "r"(v.w)
                 : "memory");
}
__device__ __forceinline__ int load_idx(const void* ei, long long pos, int is64) {
    if (is64) return (int)__ldg((const long long*)ei + pos);
    return __ldg((const int*)ei + pos);
}
__device__ __forceinline__ u64 pack2(float s) {
    u64 r; asm("mov.b64 %0, {%1, %1};" : "=l"(r) : "f"(s)); return r;
}
__device__ __forceinline__ void fma2(u64& d, u64 a, u64 b) {
    asm("fma.rn.f32x2 %0, %1, %2, %0;" : "+l"(d) : "l"(a), "l"(b));
}
__device__ __forceinline__ float2 unpack2(u64 v) {
    float2 r; asm("mov.b64 {%0, %1}, %2;" : "=f"(r.x), "=f"(r.y) : "l"(v)); return r;
}
// dual-node row FMA: weight row loaded from shared ONCE, used for both nodes
__device__ __forceinline__ void row_fma2n(u64 a0[16], u64 a1[16], const float* Ws,
                                          int k, u64 s0, u64 s1) {
    const u64* w = (const u64*)(Ws + k * 32);
#pragma unroll
    for (int j = 0; j < 16; j++) {
        u64 ww = w[j];
        fma2(a0[j], s0, ww);
        fma2(a1[j], s1, ww);
    }
}
__device__ __forceinline__ float2 h2f(u32 w) {
    __half2 h = *reinterpret_cast<__half2*>(&w);
    return __half22float2(h);
}
__device__ __forceinline__ u32 f2h(float a, float b) {
    __half2 h = __floats2half2_rn(a, b);
    return *reinterpret_cast<u32*>(&h);
}

// ---------------- projY + zero + dtype: y(fp16) = x@W1[0:64] ------------------
// 2 groups of 128 threads (sign = tid>>7); each thread handles 2 nodes.
__global__ void projYZ(const unsigned int* __restrict__ p, const float* __restrict__ x,
                       const float* __restrict__ W1p, const float* __restrict__ W1n,
                       int n) {
    __shared__ float Wp[64 * 32];
    __shared__ float Wn[64 * 32];
    for (int t = threadIdx.x; t < 64 * 32; t += blockDim.x) { Wp[t] = W1p[t]; Wn[t] = W1n[t]; }
    if (blockIdx.x == 0 && threadIdx.x == 0) {
        int is64 = 1;
        for (int i = 1; i < 256; i += 2)
            if (p[i] != 0u) { is64 = 0; break; }
        g_is64 = is64;
    }
    __syncthreads();
    int sign = threadIdx.x >> 7;
    int i0 = blockIdx.x * 256 + (threadIdx.x & 127);
    int i1 = i0 + 128;
    if (i0 >= n) return;
    bool v1 = (i1 < n);
    int i1c = v1 ? i1 : i0;

    // zero scatter targets for this thread's nodes (per sign)
    {
        const uint4 z = make_uint4(0, 0, 0, 0);
        __half* asum = sign ? g_ansum : g_apsum;
        __half* lsum = sign ? g_sumn : g_sump;
        float* cnt = sign ? g_cntn : g_cntp;
        uint4* a0z = (uint4*)(asum + (size_t)i0 * 32);
        uint4* s0z = (uint4*)(lsum + (size_t)i0 * 64);
#pragma unroll
        for (int q = 0; q < 4; q++) a0z[q] = z;
#pragma unroll
        for (int q = 0; q < 8; q++) s0z[q] = z;
        cnt[i0] = 0.f;
        if (v1) {
            uint4* a1z = (uint4*)(asum + (size_t)i1 * 32);
            uint4* s1z = (uint4*)(lsum + (size_t)i1 * 64);
#pragma unroll
            for (int q = 0; q < 4; q++) a1z[q] = z;
#pragma unroll
            for (int q = 0; q < 8; q++) s1z[q] = z;
            cnt[i1] = 0.f;
        }
    }

    const float* Ws = sign ? Wn : Wp;
    const float4* x0 = (const float4*)x + (size_t)i0 * 16;
    const float4* x1 = (const float4*)x + (size_t)i1c * 16;

    u64 a0[16], a1[16];
#pragma unroll
    for (int j = 0; j < 16; j++) { a0[j] = 0ULL; a1[j] = 0ULL; }
#pragma unroll 2
    for (int kk = 0; kk < 16; kk++) {
        float4 pv = x0[kk];
        float4 qv = x1[kk];
        int k = kk * 4;
        row_fma2n(a0, a1, Ws, k + 0, pack2(pv.x), pack2(qv.x));
        row_fma2n(a0, a1, Ws, k + 1, pack2(pv.y), pack2(qv.y));
        row_fma2n(a0, a1, Ws, k + 2, pack2(pv.z), pack2(qv.z));
        row_fma2n(a0, a1, Ws, k + 3, pack2(pv.w), pack2(qv.w));
    }
    __half* yb = sign ? g_yn : g_yp;
    uint4* yo0 = (uint4*)(yb + (size_t)i0 * 32);
#pragma unroll
    for (int q = 0; q < 4; q++) {
        float2 f0 = unpack2(a0[q * 4 + 0]), f1 = unpack2(a0[q * 4 + 1]);
        float2 f2 = unpack2(a0[q * 4 + 2]), f3 = unpack2(a0[q * 4 + 3]);
        yo0[q] = make_uint4(f2h(f0.x, f0.y), f2h(f1.x, f1.y), f2h(f2.x, f2.y), f2h(f3.x, f3.y));
    }
    if (v1) {
        uint4* yo1 = (uint4*)(yb + (size_t)i1 * 32);
#pragma unroll
        for (int q = 0; q < 4; q++) {
            float2 f0 = unpack2(a1[q * 4 + 0]), f1 = unpack2(a1[q * 4 + 1]);
            float2 f2 = unpack2(a1[q * 4 + 2]), f3 = unpack2(a1[q * 4 + 3]);
            yo1[q] = make_uint4(f2h(f0.x, f0.y), f2h(f1.x, f1.y), f2h(f2.x, f2.y), f2h(f3.x, f3.y));
        }
    }
}

// ---------------- layer-1 edge scatter (fp16, 64B rows) + counts -------------
__device__ __forceinline__ void edge1_body(const void* pe, const void* ne, int E,
                                           int is64, long long item) {
    long long e2 = item >> 2;
    int c = (int)(item & 3);
    bool pos = e2 < E;
    const void* ei = pos ? pe : ne;
    long long e = pos ? e2 : e2 - E;
    const __half* y = pos ? g_yp : g_yn;
    __half* sum = pos ? g_apsum : g_ansum;
    float* cnt = pos ? g_cntp : g_cntn;
    int s = load_idx(ei, e, is64);
    int d = load_idx(ei, (long long)E + e, is64);
    uint4 v = __ldg((const uint4*)y + (size_t)s * 4 + c);
    red_add_h8((uint4*)sum + (size_t)d * 4 + c, v);
    if (c == 0) atomicAdd(cnt + d, 1.0f);
}

__global__ void edge1(const void* __restrict__ pe, const void* __restrict__ ne, int E) {
    const int is64 = g_is64;
    long long total = (long long)E * 8;  // 2E edges * 4 items (16B each)
    long long stride = (long long)gridDim.x * blockDim.x;
    long long item = (long long)blockIdx.x * blockDim.x + threadIdx.x;
    for (; item + stride < total; item += 2 * stride) {
        edge1_body(pe, ne, E, is64, item);
        edge1_body(pe, ne, E, is64, item + stride);
    }
    if (item < total) edge1_body(pe, ne, E, is64, item);
}

// ---------------- layer-1 fused: sx = x@W1[64:128]+b; zc = tanh(sum*inv+sx) --
// 2 groups of 128 threads (sign = tid>>7); each thread handles 2 nodes.
__global__ void node1(const float* __restrict__ x,
                      const float* __restrict__ W1p, const float* __restrict__ b1p,
                      const float* __restrict__ W1n, const float* __restrict__ b1n,
                      int n) {
    __shared__ float Wp[64 * 32];
    __shared__ float Wn[64 * 32];
    for (int t = threadIdx.x; t < 64 * 32; t += blockDim.x) {
        Wp[t] = W1p[64 * 32 + t];
        Wn[t] = W1n[64 * 32 + t];
    }
    __syncthreads();
    int sign = threadIdx.x >> 7;
    int i0 = blockIdx.x * 256 + (threadIdx.x & 127);
    int i1 = i0 + 128;
    if (i0 >= n) return;
    bool v1 = (i1 < n);
    int i1c = v1 ? i1 : i0;

    const float* Ws = sign ? Wn : Wp;
    const float4* x0 = (const float4*)x + (size_t)i0 * 16;
    const float4* x1 = (const float4*)x + (size_t)i1c * 16;

    u64 a0[16], a1[16];
#pragma unroll
    for (int j = 0; j < 16; j++) { a0[j] = 0ULL; a1[j] = 0ULL; }
#pragma unroll 2
    for (int kk = 0; kk < 16; kk++) {
        float4 pv = x0[kk];
        float4 qv = x1[kk];
        int k = kk * 4;
        row_fma2n(a0, a1, Ws, k + 0, pack2(pv.x), pack2(qv.x));
        row_fma2n(a0, a1, Ws, k + 1, pack2(pv.y), pack2(qv.y));
        row_fma2n(a0, a1, Ws, k + 2, pack2(pv.z), pack2(qv.z));
        row_fma2n(a0, a1, Ws, k + 3, pack2(pv.w), pack2(qv.w));
    }

    const float* cnt = sign ? g_cntn : g_cntp;
    const __half* asum = sign ? g_ansum : g_apsum;
    const float2* bb = (const float2*)(sign ? b1n : b1p);
    float inv0 = 1.f / fmaxf(cnt[i0], 1.f);
    float inv1 = 1.f / fmaxf(cnt[i1c], 1.f);
    int ho = sign ? 4 : 0;

    // node i0
    {
        const uint4* ar = (const uint4*)(asum + (size_t)i0 * 32);
        uint4* zo = (uint4*)g_zc + (size_t)i0 * 8 + ho;
#pragma unroll
        for (int q = 0; q < 4; q++) {
            uint4 av = __ldg(ar + q);
            u32 w[4];
#pragma unroll
            for (int j = 0; j < 4; j++) {
                float2 s = unpack2(a0[q * 4 + j]);
                float2 b = __ldg(bb + q * 4 + j);
                float2 m = h2f(j == 0 ? av.x : (j == 1 ? av.y : (j == 2 ? av.z : av.w)));
                w[j] = f2h(tanhf(fmaf(m.x, inv0, s.x + b.x)),
                           tanhf(fmaf(m.y, inv0, s.y + b.y)));
            }
            zo[q] = make_uint4(w[0], w[1], w[2], w[3]);
        }
    }
    // node i1
    if (v1) {
        const uint4* ar = (const uint4*)(asum + (size_t)i1 * 32);
        uint4* zo = (uint4*)g_zc + (size_t)i1 * 8 + ho;
#pragma unroll
        for (int q = 0; q < 4; q++) {
            uint4 av = __ldg(ar + q);
            u32 w[4];
#pragma unroll
            for (int j = 0; j < 4; j++) {
                float2 s = unpack2(a1[q * 4 + j]);
                float2 b = __ldg(bb + q * 4 + j);
                float2 m = h2f(j == 0 ? av.x : (j == 1 ? av.y : (j == 2 ? av.z : av.w)));
                w[j] = f2h(tanhf(fmaf(m.x, inv1, s.x + b.x)),
                           tanhf(fmaf(m.y, inv1, s.y + b.y)));
            }
            zo[q] = make_uint4(w[0], w[1], w[2], w[3]);
        }
    }
}

// ---------------- layer-2 edge scatter (fp16 zc rows, 128B) ------------------
__device__ __forceinline__ void edge2_body(const void* pe, const void* ne, int E,
                                           int is64, long long item) {
    long long e2 = item >> 3;
    int c = (int)(item & 7);
    bool pos = e2 < E;
    const void* ei = pos ? pe : ne;
    long long e = pos ? e2 : e2 - E;
    __half* sum = pos ? g_sump : g_sumn;
    int s = load_idx(ei, e, is64);
    int d = load_idx(ei, (long long)E + e, is64);
    uint4 v = __ldg((const uint4*)g_zc + (size_t)s * 8 + c);
    red_add_h8((uint4*)sum + (size_t)d * 8 + c, v);
}

__global__ void edge2(const void* __restrict__ pe, const void* __restrict__ ne, int E) {
    const int is64 = g_is64;
    long long total = (long long)E * 16;  // 2E edges * 8 items (16B each)
    long long stride = (long long)gridDim.x * blockDim.x;
    long long item = (long long)blockIdx.x * blockDim.x + threadIdx.x;
    for (; item + stride < total; item += 2 * stride) {
        edge2_body(pe, ne, E, is64, item);
        edge2_body(pe, ne, E, is64, item + stride);
    }
    if (item < total) edge2_body(pe, ne, E, is64, item);
}

// ---------------- layer-2 dual-node GEMM section ------------------------------
__device__ __forceinline__ void gemm_sec2n(u64 a0[16], u64 a1[16], const float* Ws,
                                           int kbase, const uint4* s0p, const uint4* s1p,
                                           float sc0, float sc1) {
#pragma unroll
    for (int q = 0; q < 4; q++) {
        uint4 u0 = __ldg(s0p + q);
        uint4 u1 = __ldg(s1p + q);
        int k = kbase + q * 8;
        float2 f0, f1;
        f0 = h2f(u0.x); f1 = h2f(u1.x);
        row_fma2n(a0, a1, Ws, k + 0, pack2(f0.x * sc0), pack2(f1.x * sc1));
        row_fma2n(a0, a1, Ws, k + 1, pack2(f0.y * sc0), pack2(f1.y * sc1));
        f0 = h2f(u0.y); f1 = h2f(u1.y);
        row_fma2n(a0, a1, Ws, k + 2, pack2(f0.x * sc0), pack2(f1.x * sc1));
        row_fma2n(a0, a1, Ws, k + 3, pack2(f0.y * sc0), pack2(f1.y * sc1));
        f0 = h2f(u0.z); f1 = h2f(u1.z);
        row_fma2n(a0, a1, Ws, k + 4, pack2(f0.x * sc0), pack2(f1.x * sc1));
        row_fma2n(a0, a1, Ws, k + 5, pack2(f0.y * sc0), pack2(f1.y * sc1));
        f0 = h2f(u0.w); f1 = h2f(u1.w);
        row_fma2n(a0, a1, Ws, k + 6, pack2(f0.x * sc0), pack2(f1.x * sc1));
        row_fma2n(a0, a1, Ws, k + 7, pack2(f0.y * sc0), pack2(f1.y * sc1));
    }
}

// ---------------- layer-2 node GEMM -> output (2-node blocked) ----------------
// 2 groups of 128 threads: sign = tid>>7; each thread does nodes i and i+128.
__global__ void node_l2(const float* __restrict__ W2p, const float* __restrict__ b2p,
                        const float* __restrict__ W2n, const float* __restrict__ b2n,
                        float* __restrict__ out, int n) {
    __shared__ float Wp[96 * 32];
    __shared__ float Wn[96 * 32];
    for (int t = threadIdx.x; t < 96 * 32; t += blockDim.x) { Wp[t] = W2p[t]; Wn[t] = W2n[t]; }
    __syncthreads();
    int sign = threadIdx.x >> 7;
    int i0 = blockIdx.x * 256 + (threadIdx.x & 127);
    int i1 = i0 + 128;
    if (i0 >= n) return;
    bool v1 = (i1 < n);
    int i1c = v1 ? i1 : i0;

    float invp0 = 1.f / fmaxf(g_cntp[i0], 1.f);
    float invn0 = 1.f / fmaxf(g_cntn[i0], 1.f);
    float invp1 = 1.f / fmaxf(g_cntp[i1c], 1.f);
    float invn1 = 1.f / fmaxf(g_cntn[i1c], 1.f);

    int ho = sign ? 4 : 0;
    // pos sign: [szpp*invp, sznn*invn, zp];  neg sign: [sznp*invp, szpn*invn, zn]
    const uint4* s0a = (const uint4*)g_sump + (size_t)i0 * 8 + ho;
    const uint4* s1a = (const uint4*)g_sumn + (size_t)i0 * 8 + (4 - ho);
    const uint4* s2a = (const uint4*)g_zc   + (size_t)i0 * 8 + ho;
    const uint4* s0b = (const uint4*)g_sump + (size_t)i1c * 8 + ho;
    const uint4* s1b = (const uint4*)g_sumn + (size_t)i1c * 8 + (4 - ho);
    const uint4* s2b = (const uint4*)g_zc   + (size_t)i1c * 8 + ho;
    const float* Ws = sign ? Wn : Wp;

    u64 a0[16], a1[16];
#pragma unroll
    for (int j = 0; j < 16; j++) { a0[j] = 0ULL; a1[j] = 0ULL; }
    gemm_sec2n(a0, a1, Ws, 0,  s0a, s0b, invp0, invp1);
    gemm_sec2n(a0, a1, Ws, 32, s1a, s1b, invn0, invn1);
    gemm_sec2n(a0, a1, Ws, 64, s2a, s2b, 1.0f, 1.0f);

    const float2* bb = (const float2*)(sign ? b2n : b2p);
    float2* o0 = (float2*)(out + (size_t)i0 * 64 + (sign ? 32 : 0));
    float2* o1 = (float2*)(out + (size_t)i1 * 64 + (sign ? 32 : 0));
#pragma unroll
    for (int j = 0; j < 16; j++) {
        float2 b = __ldg(bb + j);
        float2 f = unpack2(a0[j]);
        o0[j] = make_float2(tanhf(f.x + b.x), tanhf(f.y + b.y));
        if (v1) {
            f = unpack2(a1[j]);
            o1[j] = make_float2(tanhf(f.x + b.x), tanhf(f.y + b.y));
        }
    }
}

// ---------------- launch ------------------------------------------------------
extern "C" void kernel_launch(void* const* d_in, const int* in_sizes, int n_in,
                              void* d_out, int out_size) {
    const float* x   = (const float*)d_in[0];
    const float* W1p = (const float*)d_in[1];
    const float* b1p = (const float*)d_in[2];
    const float* W1n = (const float*)d_in[3];
    const float* b1n = (const float*)d_in[4];
    const float* W2p = (const float*)d_in[5];
    const float* b2p = (const float*)d_in[6];
    const float* W2n = (const float*)d_in[7];
    const float* b2n = (const float*)d_in[8];
    const void* pe = d_in[9];
    const void* ne = d_in[10];

    int n = in_sizes[0] / 64;
    int E = in_sizes[9] / 2;
    float* out = (float*)d_out;

    projYZ<<<(n + 255) / 256, 256>>>((const unsigned int*)pe, x, W1p, W1n, n);
    edge1<<<4736, 256>>>(pe, ne, E);
    node1<<<(n + 255) / 256, 256>>>(x, W1p, b1p, W1n, b1n, n);
    edge2<<<4736, 256>>>(pe, ne, E);
    node_l2<<<(n + 255) / 256, 256>>>(W2p, b2p, W2n, b2n, out, n);
}